// round 12
// baseline (speedup 1.0000x reference)
#include <cuda_runtime.h>
#include <cuda_fp16.h>
#include <cstdint>
#include <cstddef>

#define B_GR 256
#define N_PG 64
#define D_DIM 256
#define T_TOT 16384
#define E_TOT 524288
#define E_PG 2048
#define BOND_D 16
#define SLOPE 0.22916666666666666f
// activations stored scaled by 1/16 in fp16 (exact power-of-2)
#define OSC_F 0.0625f
#define SC_F 16.0f

__device__ __half g_eb1[134217728];
__device__ __half g_eb2[134217728];
__device__ __half g_yz[8388608];          // [T][512] fp16 (scaled): y | z
__device__ __half g_xm1[4194304];         // scaled xm
__device__ __half g_xm2[4194304];
__device__ __half g_wcat1[131072];        // [256][512] fp16 = Wn | Ws
__device__ __half g_wcat2[131072];
__device__ __half g_wf1[327680];          // fp16 Wf: x16, sum-rows x1024
__device__ __half g_wf2[327680];
__device__ __half g_r1[B_GR * 1280];      // scaled readout
__device__ __half g_r2[B_GR * 1280];
__device__ float g_xlast1[T_TOT];         // fp32 argsort key (scale-invariant)
__device__ float g_xlast2[T_TOT];
__device__ float g_o1[B_GR * D_DIM];
__device__ float g_o2[B_GR * D_DIM];
__device__ float g_fus[B_GR * 6];
__device__ int g_ptr1[T_TOT + 1];
__device__ int g_ptr2[T_TOT + 1];
__device__ int2 g_pack1[E_TOT];
__device__ int2 g_pack2[E_TOT];
__device__ int g_is64[2];

// ---- index dtype detection: int64 LE => odd 32-bit words all zero ----
__global__ void detect_kernel(const unsigned* e1, const unsigned* e2) {
    __shared__ int ok[2];
    int t = threadIdx.x;
    if (t < 2) ok[t] = 1;
    __syncthreads();
    if (e1[2 * t + 1]) ok[0] = 0;
    if (e2[2 * t + 1]) ok[1] = 0;
    __syncthreads();
    if (t < 2) g_is64[t] = ok[t];
}

__device__ __forceinline__ int loadIdx(const void* p, int is64, long long i) {
    return is64 ? (int)((const long long*)p)[i] : ((const int*)p)[i];
}

// ---- per-graph CSR, dst-grouped, stable order ----
__global__ void build_csr(const void* __restrict__ eidx, int which,
                          int* __restrict__ ptr, int2* __restrict__ pack) {
    __shared__ int sl[E_PG], dl[E_PG], cnt[N_PG], base[N_PG];
    int g = blockIdx.x, t = threadIdx.x;
    int is64 = g_is64[which];
    if (t < N_PG) cnt[t] = 0;
    __syncthreads();
    for (int e = t; e < E_PG; e += blockDim.x) {
        long long ge = (long long)g * E_PG + e;
        sl[e] = loadIdx(eidx, is64, ge) - g * N_PG;
        int d = loadIdx(eidx, is64, (long long)E_TOT + ge) - g * N_PG;
        dl[e] = d;
        atomicAdd(&cnt[d], 1);
    }
    __syncthreads();
    if (t == 0) {
        int run = 0;
        for (int n = 0; n < N_PG; n++) {
            base[n] = run;
            ptr[g * N_PG + n] = g * E_PG + run;
            run += cnt[n];
        }
        if (g == 0) ptr[T_TOT] = E_TOT;
    }
    __syncthreads();
    if (t < N_PG) {
        int p = g * E_PG + base[t];
        for (int e = 0; e < E_PG; e++)
            if (dl[e] == t) { pack[p] = make_int2((g * E_PG + e) * D_DIM, sl[e] * D_DIM); p++; }
    }
}

// ---- weight packs (fp16 out) ----
__global__ void pack2_kernel(const float* __restrict__ Wn, const float* __restrict__ Ws,
                             __half* __restrict__ Wcat) {
    int k = blockIdx.x, t = threadIdx.x;
    Wcat[k * 512 + t] = __float2half_rn(Wn[k * 256 + t]);
    Wcat[k * 512 + 256 + t] = __float2half_rn(Ws[k * 256 + t]);
}
// Wf: x16 undoes activation scaling; sum-channel rows additionally x64 (sum fed as mean)
__global__ void packwf_kernel(const float* __restrict__ Wf, __half* __restrict__ dst) {
    int k = blockIdx.x, t = threadIdx.x;
    float sc = (k >= 256 && k < 512) ? 1024.f : 16.f;
    dst[k * 256 + t] = __float2half_rn(Wf[k * 256 + t] * sc);
}

// ---- ptx helpers ----
__device__ __forceinline__ uint32_t su32(const void* p) {
    return (uint32_t)__cvta_generic_to_shared(p);
}
__device__ __forceinline__ void ldsm4(uint32_t* r, uint32_t addr) {
    asm volatile("ldmatrix.sync.aligned.m8n8.x4.shared.b16 {%0,%1,%2,%3}, [%4];"
                 : "=r"(r[0]), "=r"(r[1]), "=r"(r[2]), "=r"(r[3]) : "r"(addr));
}
__device__ __forceinline__ void ldsm4t(uint32_t* r, uint32_t addr) {
    asm volatile("ldmatrix.sync.aligned.m8n8.x4.trans.shared.b16 {%0,%1,%2,%3}, [%4];"
                 : "=r"(r[0]), "=r"(r[1]), "=r"(r[2]), "=r"(r[3]) : "r"(addr));
}
__device__ __forceinline__ void mma16816(float* c, const uint32_t* a, uint32_t b0, uint32_t b1) {
    asm volatile(
        "mma.sync.aligned.m16n8k16.row.col.f32.f16.f16.f32 "
        "{%0,%1,%2,%3},{%4,%5,%6,%7},{%8,%9},{%0,%1,%2,%3};"
        : "+f"(c[0]), "+f"(c[1]), "+f"(c[2]), "+f"(c[3])
        : "r"(a[0]), "r"(a[1]), "r"(a[2]), "r"(a[3]), "r"(b0), "r"(b1));
}

#define A_PAD 24
#define B_PAD 136

// ---- fp16 tensor-core GEMM: C = osc * act(A@B + bias), fp32 accum ----
// HIN: inputs already fp16. OSC: scale output by 1/16 (activation scaling).
template <int ACT, bool HIN, bool OSC, typename OutT>
__global__ void __launch_bounds__(256) hgemm(const void* __restrict__ Av,
                                             const void* __restrict__ Bv,
                                             const float* __restrict__ bias,
                                             OutT* __restrict__ C,
                                             int M, int N, int K) {
    __shared__ __align__(16) __half As[2][128 * A_PAD];
    __shared__ __align__(16) __half Bs[2][16 * B_PAD];
    int tid = threadIdx.x;
    int wid = tid >> 5, lane = tid & 31;
    int gid = lane >> 2, tg = lane & 3;
    int row0 = blockIdx.y * 128, col0 = blockIdx.x * 128;
    int wrow = (wid & 3) * 32, wcol = (wid >> 2) * 64;
    int arow = tid >> 1, ak = (tid & 1) * 8;
    int bkr = tid >> 5, bcol = (tid & 31) * 4;

    const float* Af = (const float*)Av;
    const float* Bf = (const float*)Bv;
    const __half* Ah = (const __half*)Av;
    const __half* Bh = (const __half*)Bv;

    uint32_t aad[2][2], bad[2];
    {
        int arw = (lane & 15), acl = (lane >> 4) * 8;
        int bk = (lane & 7) + ((lane >> 4) & 1) * 8;
        int bn = wcol + ((lane >> 3) & 1) * 8;
#pragma unroll
        for (int b = 0; b < 2; b++) {
            aad[b][0] = su32(&As[b][(wrow + arw) * A_PAD + acl]);
            aad[b][1] = su32(&As[b][(wrow + 16 + arw) * A_PAD + acl]);
            bad[b] = su32(&Bs[b][bk * B_PAD + bn]);
        }
    }

    float acc[2][8][4];
#pragma unroll
    for (int i = 0; i < 2; i++)
#pragma unroll
        for (int j = 0; j < 8; j++)
#pragma unroll
            for (int q = 0; q < 4; q++) acc[i][j][q] = 0.f;

    if constexpr (HIN) {
        uint4 av = *(const uint4*)(Ah + (size_t)(row0 + arow) * K + ak);
        uint2 b0 = *(const uint2*)(Bh + (size_t)bkr * N + col0 + bcol);
        uint2 b1 = *(const uint2*)(Bh + (size_t)(bkr + 8) * N + col0 + bcol);
        *(uint4*)&As[0][arow * A_PAD + ak] = av;
        *(uint2*)&Bs[0][bkr * B_PAD + bcol] = b0;
        *(uint2*)&Bs[0][(bkr + 8) * B_PAD + bcol] = b1;
    } else {
        float4 a0 = *(const float4*)(Af + (size_t)(row0 + arow) * K + ak);
        float4 a1 = *(const float4*)(Af + (size_t)(row0 + arow) * K + ak + 4);
        float4 b0 = *(const float4*)(Bf + (size_t)bkr * N + col0 + bcol);
        float4 b1 = *(const float4*)(Bf + (size_t)(bkr + 8) * N + col0 + bcol);
        __half2 h0 = __floats2half2_rn(a0.x, a0.y), h1 = __floats2half2_rn(a0.z, a0.w);
        __half2 h2 = __floats2half2_rn(a1.x, a1.y), h3 = __floats2half2_rn(a1.z, a1.w);
        uint4 u; u.x = *(uint32_t*)&h0; u.y = *(uint32_t*)&h1; u.z = *(uint32_t*)&h2; u.w = *(uint32_t*)&h3;
        *(uint4*)&As[0][arow * A_PAD + ak] = u;
        __half2 p0 = __floats2half2_rn(b0.x, b0.y), p1 = __floats2half2_rn(b0.z, b0.w);
        uint2 v; v.x = *(uint32_t*)&p0; v.y = *(uint32_t*)&p1;
        *(uint2*)&Bs[0][bkr * B_PAD + bcol] = v;
        p0 = __floats2half2_rn(b1.x, b1.y); p1 = __floats2half2_rn(b1.z, b1.w);
        v.x = *(uint32_t*)&p0; v.y = *(uint32_t*)&p1;
        *(uint2*)&Bs[0][(bkr + 8) * B_PAD + bcol] = v;
    }
    __syncthreads();

    int NT = K >> 4;
    int buf = 0;
    for (int kt = 0; kt < NT; kt++) {
        uint4 pau; uint2 pb0u, pb1u;
        float4 paf0, paf1, pbf0, pbf1;
        if (kt + 1 < NT) {
            if constexpr (HIN) {
                pau = *(const uint4*)(Ah + (size_t)(row0 + arow) * K + ak + (kt + 1) * 16);
                pb0u = *(const uint2*)(Bh + (size_t)(bkr + (kt + 1) * 16) * N + col0 + bcol);
                pb1u = *(const uint2*)(Bh + (size_t)(bkr + 8 + (kt + 1) * 16) * N + col0 + bcol);
            } else {
                paf0 = *(const float4*)(Af + (size_t)(row0 + arow) * K + ak + (kt + 1) * 16);
                paf1 = *(const float4*)(Af + (size_t)(row0 + arow) * K + ak + (kt + 1) * 16 + 4);
                pbf0 = *(const float4*)(Bf + (size_t)(bkr + (kt + 1) * 16) * N + col0 + bcol);
                pbf1 = *(const float4*)(Bf + (size_t)(bkr + 8 + (kt + 1) * 16) * N + col0 + bcol);
            }
        }
        uint32_t a[2][4], bf16[4][4];
        ldsm4(a[0], aad[buf][0]);
        ldsm4(a[1], aad[buf][1]);
#pragma unroll
        for (int jp = 0; jp < 4; jp++) ldsm4t(bf16[jp], bad[buf] + jp * 32);
#pragma unroll
        for (int i = 0; i < 2; i++)
#pragma unroll
            for (int j = 0; j < 8; j++)
                mma16816(acc[i][j], a[i], bf16[j >> 1][j & 1], bf16[j >> 1][2 + (j & 1)]);
        if (kt + 1 < NT) {
            buf ^= 1;
            if constexpr (HIN) {
                *(uint4*)&As[buf][arow * A_PAD + ak] = pau;
                *(uint2*)&Bs[buf][bkr * B_PAD + bcol] = pb0u;
                *(uint2*)&Bs[buf][(bkr + 8) * B_PAD + bcol] = pb1u;
            } else {
                __half2 h0 = __floats2half2_rn(paf0.x, paf0.y), h1 = __floats2half2_rn(paf0.z, paf0.w);
                __half2 h2 = __floats2half2_rn(paf1.x, paf1.y), h3 = __floats2half2_rn(paf1.z, paf1.w);
                uint4 u; u.x = *(uint32_t*)&h0; u.y = *(uint32_t*)&h1; u.z = *(uint32_t*)&h2; u.w = *(uint32_t*)&h3;
                *(uint4*)&As[buf][arow * A_PAD + ak] = u;
                __half2 p0 = __floats2half2_rn(pbf0.x, pbf0.y), p1 = __floats2half2_rn(pbf0.z, pbf0.w);
                uint2 v; v.x = *(uint32_t*)&p0; v.y = *(uint32_t*)&p1;
                *(uint2*)&Bs[buf][bkr * B_PAD + bcol] = v;
                p0 = __floats2half2_rn(pbf1.x, pbf1.y); p1 = __floats2half2_rn(pbf1.z, pbf1.w);
                v.x = *(uint32_t*)&p0; v.y = *(uint32_t*)&p1;
                *(uint2*)&Bs[buf][(bkr + 8) * B_PAD + bcol] = v;
            }
            __syncthreads();
        }
    }

#pragma unroll
    for (int j = 0; j < 8; j++) {
        int c = col0 + wcol + j * 8 + tg * 2;
        float b0v = 0.f, b1v = 0.f;
        if (bias) { float2 bb = *(const float2*)(bias + c); b0v = bb.x; b1v = bb.y; }
#pragma unroll
        for (int i = 0; i < 2; i++) {
            int ra = row0 + wrow + i * 16 + gid;
            float v0 = acc[i][j][0] + b0v, v1 = acc[i][j][1] + b1v;
            float v2 = acc[i][j][2] + b0v, v3 = acc[i][j][3] + b1v;
            if (ACT == 2) {
                v0 = v0 >= 0.f ? v0 : SLOPE * v0; v1 = v1 >= 0.f ? v1 : SLOPE * v1;
                v2 = v2 >= 0.f ? v2 : SLOPE * v2; v3 = v3 >= 0.f ? v3 : SLOPE * v3;
            }
            if (OSC) { v0 *= OSC_F; v1 *= OSC_F; v2 *= OSC_F; v3 *= OSC_F; }
            if constexpr (sizeof(OutT) == 2) {
                *(__half2*)((__half*)C + (size_t)ra * N + c) = __floats2half2_rn(v0, v1);
                *(__half2*)((__half*)C + (size_t)(ra + 8) * N + c) = __floats2half2_rn(v2, v3);
            } else {
                *(float2*)((float*)C + (size_t)ra * N + c) = make_float2(v0, v1);
                *(float2*)((float*)C + (size_t)(ra + 8) * N + c) = make_float2(v2, v3);
            }
        }
    }
}

// ---- conv: fp32 math on scaled fp16 streams ----
// xo_s = relu(16*z_s + sum relu(16*y_s + eb) + bs) / 16
__global__ void conv_kernel(const __half* __restrict__ yz,
                            const __half* __restrict__ eb, const int* __restrict__ ptr,
                            const int2* __restrict__ pack, const float* __restrict__ bs,
                            __half* __restrict__ xo, float* __restrict__ xlast) {
    extern __shared__ __half ys[];   // 64 x 256 fp16 = 32 KB
    int g = blockIdx.x, t = threadIdx.x;
    const __half* yg = yz + (size_t)g * N_PG * 512;
    for (int i = t; i < N_PG * 32; i += 256) {
        int n = i >> 5, c = (i & 31) * 8;
        *(uint4*)&ys[n * 256 + c] = *(const uint4*)(yg + (size_t)n * 512 + c);
    }
    __syncthreads();
    int q = t >> 6, dd = (t & 63) * 4;
    float4 bsv = *(const float4*)(bs + dd);
    for (int n = q; n < N_PG; n += 4) {
        int p0 = ptr[g * N_PG + n], p1 = ptr[g * N_PG + n + 1];
        float ax = 0.f, ay = 0.f, az = 0.f, aw = 0.f;
#pragma unroll 2
        for (int j = p0; j < p1; j++) {
            int2 pr = pack[j];
            uint2 yv = *(const uint2*)(ys + pr.y + dd);
            uint2 ev = *(const uint2*)(eb + (size_t)pr.x + dd);
            float2 y0 = __half22float2(*(__half2*)&yv.x), y1 = __half22float2(*(__half2*)&yv.y);
            float2 e0 = __half22float2(*(__half2*)&ev.x), e1 = __half22float2(*(__half2*)&ev.y);
            ax += fmaxf(fmaf(SC_F, y0.x, e0.x), 0.f);
            ay += fmaxf(fmaf(SC_F, y0.y, e0.y), 0.f);
            az += fmaxf(fmaf(SC_F, y1.x, e1.x), 0.f);
            aw += fmaxf(fmaf(SC_F, y1.y, e1.y), 0.f);
        }
        uint2 zv2 = *(const uint2*)(yg + (size_t)n * 512 + 256 + dd);
        float2 z0 = __half22float2(*(__half2*)&zv2.x), z1 = __half22float2(*(__half2*)&zv2.y);
        float rx = fmaxf(fmaf(SC_F, z0.x, ax + bsv.x), 0.f);
        float ry = fmaxf(fmaf(SC_F, z0.y, ay + bsv.y), 0.f);
        float rz = fmaxf(fmaf(SC_F, z1.x, az + bsv.z), 0.f);
        float rw = fmaxf(fmaf(SC_F, z1.y, aw + bsv.w), 0.f);
        size_t o = (size_t)(g * N_PG + n) * D_DIM + dd;
        __half2 o0 = __floats2half2_rn(rx * OSC_F, ry * OSC_F);
        __half2 o1 = __floats2half2_rn(rz * OSC_F, rw * OSC_F);
        uint2 ov; ov.x = *(uint32_t*)&o0; ov.y = *(uint32_t*)&o1;
        *(uint2*)(xo + o) = ov;
        if ((t & 63) == 63) xlast[g * N_PG + n] = rw;   // fp32 key, ordering exact
    }
}

// ---- dot_pool via mma on scaled inputs; outputs x256 = SC^2 ----
__global__ void __launch_bounds__(256) dotpool_kernel(const __half* __restrict__ x1,
                                                      const __half* __restrict__ x2,
                                                      float* __restrict__ fus, int s) {
    extern __shared__ __half sm_h[];
    __half* a = sm_h;            // [64][264]
    __half* b = sm_h + 64 * 264; // [64][264]
    __shared__ float rm[256], rs[256];
    int g = blockIdx.x, t = threadIdx.x;
    int wid = t >> 5, lane = t & 31;
    const __half* p1 = x1 + (size_t)g * N_PG * D_DIM;
    const __half* p2 = x2 + (size_t)g * N_PG * D_DIM;
    for (int i = t; i < 2048; i += 256) {
        int n = i >> 5, c = (i & 31) * 8;
        *(uint4*)&a[n * 264 + c] = *(const uint4*)(p1 + (size_t)n * 256 + c);
        *(uint4*)&b[n * 264 + c] = *(const uint4*)(p2 + (size_t)n * 256 + c);
    }
    __syncthreads();
    int rt = (wid & 3) * 16, cb = (wid >> 2) * 32;
    uint32_t aaddr = su32(&a[(rt + (lane & 15)) * 264 + (lane >> 4) * 8]);
    uint32_t baddr0 = su32(&b[(cb + (lane & 7) + ((lane >> 4) & 1) * 8) * 264 + ((lane >> 3) & 1) * 8]);
    uint32_t baddr1 = baddr0 + 16 * 264 * 2;
    float acc[4][4];
#pragma unroll
    for (int i = 0; i < 4; i++)
#pragma unroll
        for (int j = 0; j < 4; j++) acc[i][j] = 0.f;
#pragma unroll
    for (int kk = 0; kk < 16; kk++) {
        uint32_t af[4], b0[4], b1[4];
        ldsm4(af, aaddr + kk * 32);
        ldsm4(b0, baddr0 + kk * 32);
        ldsm4(b1, baddr1 + kk * 32);
        mma16816(acc[0], af, b0[0], b0[1]);
        mma16816(acc[1], af, b0[2], b0[3]);
        mma16816(acc[2], af, b1[0], b1[1]);
        mma16816(acc[3], af, b1[2], b1[3]);
    }
    float lmax = -3.4e38f, ls = 0.f;
#pragma unroll
    for (int i = 0; i < 4; i++)
#pragma unroll
        for (int j = 0; j < 4; j++) { lmax = fmaxf(lmax, acc[i][j]); ls += acc[i][j]; }
    rm[t] = lmax; rs[t] = ls;
    __syncthreads();
    for (int o = 128; o > 0; o >>= 1) {
        if (t < o) { rm[t] = fmaxf(rm[t], rm[t + o]); rs[t] += rs[t + o]; }
        __syncthreads();
    }
    if (t == 0) {
        fus[g * 6 + 2 * s] = 256.f * rm[0];
        fus[g * 6 + 2 * s + 1] = 256.f * rs[0] / 4096.f;
    }
}

// ---- readout (scaled domain): [mean_s, mean_s, top-3 rows_s] -> fp16 [B,1280] ----
__global__ void readout_kernel(const __half* __restrict__ x, const float* __restrict__ xl,
                               __half* __restrict__ r) {
    __shared__ int ord[3];
    int g = blockIdx.x, t = threadIdx.x;
    const __half* xg = x + (size_t)g * N_PG * D_DIM;
    float s = 0.f;
    for (int n = 0; n < N_PG; n++) s += __half2float(xg[n * D_DIM + t]);
    __half m = __float2half_rn(s / 64.f);
    r[g * 1280 + t] = m;
    r[g * 1280 + 256 + t] = m;   // sum channel as mean_s; Wf rows x1024
    if (t < 32) {
        float v0 = xl[g * N_PG + t], v1 = xl[g * N_PG + t + 32];
        int i0 = t, i1 = t + 32;
        for (int k = 0; k < 3; k++) {
            float cv; int bi;
            if (v0 > v1 || (v0 == v1 && i0 < i1)) { cv = v0; bi = i0; } else { cv = v1; bi = i1; }
            for (int o = 16; o > 0; o >>= 1) {
                float ov = __shfl_down_sync(0xffffffffu, cv, o);
                int oi = __shfl_down_sync(0xffffffffu, bi, o);
                if (ov > cv || (ov == cv && oi < bi)) { cv = ov; bi = oi; }
            }
            bi = __shfl_sync(0xffffffffu, bi, 0);
            if (t == 0) ord[k] = bi;
            if (bi == i0) v0 = -3.4e38f;
            if (bi == i1) v1 = -3.4e38f;
        }
    }
    __syncthreads();
    for (int k = 0; k < 3; k++) r[g * 1280 + 512 + k * 256 + t] = xg[ord[k] * D_DIM + t];
}

// ---- head ----
__global__ void head_kernel(const float* __restrict__ o1, const float* __restrict__ o2,
                            const float* __restrict__ fus, const float* __restrict__ Wo1,
                            const float* __restrict__ bo1, const float* __restrict__ Wo2,
                            const float* __restrict__ bo2, float* __restrict__ out) {
    __shared__ float cat[518];
    __shared__ float r0[256], r1a[256];
    int g = blockIdx.x, t = threadIdx.x;
    cat[t] = o1[g * 256 + t];
    cat[256 + t] = o2[g * 256 + t];
    if (t < 6) cat[512 + t] = fus[g * 6 + t];
    __syncthreads();
    float h = bo1[t];
    for (int k = 0; k < 518; k++) h += cat[k] * Wo1[k * 256 + t];
    r0[t] = h * Wo2[t * 2];
    r1a[t] = h * Wo2[t * 2 + 1];
    __syncthreads();
    for (int o = 128; o > 0; o >>= 1) {
        if (t < o) { r0[t] += r0[t + o]; r1a[t] += r1a[t + o]; }
        __syncthreads();
    }
    if (t == 0) { out[g * 2] = r0[0] + bo2[0]; out[g * 2 + 1] = r1a[0] + bo2[1]; }
}

extern "C" void kernel_launch(void* const* d_in, const int* in_sizes, int n_in,
                              void* d_out, int out_size) {
    const float* x1 = (const float*)d_in[0];
    const void* ei1 = d_in[1];
    const float* ea1 = (const float*)d_in[2];
    const float* x2 = (const float*)d_in[4];
    const void* ei2 = d_in[5];
    const float* ea2 = (const float*)d_in[6];
    const float* W0_1 = (const float*)d_in[8];  const float* b0_1 = (const float*)d_in[9];
    const float* W0_2 = (const float*)d_in[10]; const float* b0_2 = (const float*)d_in[11];
    const float* Wn1 = (const float*)d_in[12];  const float* We1 = (const float*)d_in[13];
    const float* bm1 = (const float*)d_in[14];  const float* Ws1 = (const float*)d_in[15];
    const float* bs1 = (const float*)d_in[16];
    const float* Wn2 = (const float*)d_in[17];  const float* We2 = (const float*)d_in[18];
    const float* bm2 = (const float*)d_in[19];  const float* Ws2 = (const float*)d_in[20];
    const float* bs2 = (const float*)d_in[21];
    const float* Wf1 = (const float*)d_in[22];  const float* bf1 = (const float*)d_in[23];
    const float* Wf2 = (const float*)d_in[24];  const float* bf2 = (const float*)d_in[25];
    const float* Wo1 = (const float*)d_in[26];  const float* bo1 = (const float*)d_in[27];
    const float* Wo2 = (const float*)d_in[28];  const float* bo2 = (const float*)d_in[29];
    float* out = (float*)d_out;

    void* p;
    cudaGetSymbolAddress(&p, g_eb1);   __half* eb1 = (__half*)p;
    cudaGetSymbolAddress(&p, g_eb2);   __half* eb2 = (__half*)p;
    cudaGetSymbolAddress(&p, g_yz);    __half* yz = (__half*)p;
    cudaGetSymbolAddress(&p, g_xm1);   __half* xm1 = (__half*)p;
    cudaGetSymbolAddress(&p, g_xm2);   __half* xm2 = (__half*)p;
    cudaGetSymbolAddress(&p, g_wcat1); __half* wc1 = (__half*)p;
    cudaGetSymbolAddress(&p, g_wcat2); __half* wc2 = (__half*)p;
    cudaGetSymbolAddress(&p, g_wf1);   __half* wf1 = (__half*)p;
    cudaGetSymbolAddress(&p, g_wf2);   __half* wf2 = (__half*)p;
    cudaGetSymbolAddress(&p, g_r1);    __half* r1 = (__half*)p;
    cudaGetSymbolAddress(&p, g_r2);    __half* r2 = (__half*)p;
    cudaGetSymbolAddress(&p, g_xlast1); float* xl1 = (float*)p;
    cudaGetSymbolAddress(&p, g_xlast2); float* xl2 = (float*)p;
    cudaGetSymbolAddress(&p, g_o1);    float* o1 = (float*)p;
    cudaGetSymbolAddress(&p, g_o2);    float* o2 = (float*)p;
    cudaGetSymbolAddress(&p, g_fus);   float* fus = (float*)p;
    cudaGetSymbolAddress(&p, g_ptr1);  int* ptr1 = (int*)p;
    cudaGetSymbolAddress(&p, g_ptr2);  int* ptr2 = (int*)p;
    cudaGetSymbolAddress(&p, g_pack1); int2* pack1 = (int2*)p;
    cudaGetSymbolAddress(&p, g_pack2); int2* pack2 = (int2*)p;

    cudaFuncSetAttribute(conv_kernel, cudaFuncAttributeMaxDynamicSharedMemorySize, 32768);
    cudaFuncSetAttribute(dotpool_kernel, cudaFuncAttributeMaxDynamicSharedMemorySize, 2 * 64 * 264 * 2);

    detect_kernel<<<1, 512>>>((const unsigned*)ei1, (const unsigned*)ei2);
    build_csr<<<B_GR, 256>>>(ei1, 0, ptr1, pack1);
    build_csr<<<B_GR, 256>>>(ei2, 1, ptr2, pack2);
    pack2_kernel<<<256, 256>>>(Wn1, Ws1, wc1);
    pack2_kernel<<<256, 256>>>(Wn2, Ws2, wc2);
    packwf_kernel<<<1280, 256>>>(Wf1, wf1);
    packwf_kernel<<<1280, 256>>>(Wf2, wf2);

    // edge bias (unscaled, ~O(1)): eb = ea @ We + bm
    dim3 gE(2, E_TOT / 128);
    hgemm<0, false, false, __half><<<gE, 256>>>(ea1, We1, bm1, eb1, E_TOT, 256, 16);
    hgemm<0, false, false, __half><<<gE, 256>>>(ea2, We2, bm2, eb2, E_TOT, 256, 16);

    // input layer, output scaled by 1/16
    dim3 gT(2, T_TOT / 128);
    hgemm<2, false, true, __half><<<gT, 256>>>(x1, W0_1, b0_1, xm1, T_TOT, 256, 128);
    hgemm<2, false, true, __half><<<gT, 256>>>(x2, W0_2, b0_2, xm2, T_TOT, 256, 128);

    dim3 gYZ(4, T_TOT / 128);   // N=512
    for (int s = 0; s < 3; s++) {
        hgemm<0, true, false, __half><<<gYZ, 256>>>(xm1, wc1, nullptr, yz, T_TOT, 512, 256);
        conv_kernel<<<B_GR, 256, 32768>>>(yz, eb1, ptr1, pack1, bs1, xm1, xl1);
        hgemm<0, true, false, __half><<<gYZ, 256>>>(xm2, wc2, nullptr, yz, T_TOT, 512, 256);
        conv_kernel<<<B_GR, 256, 32768>>>(yz, eb2, ptr2, pack2, bs2, xm2, xl2);
        dotpool_kernel<<<B_GR, 256, 2 * 64 * 264 * 2>>>(xm1, xm2, fus, s);
    }

    readout_kernel<<<B_GR, 256>>>(xm1, xl1, r1);
    readout_kernel<<<B_GR, 256>>>(xm2, xl2, r2);
    dim3 gF(2, 2);
    hgemm<0, true, false, float><<<gF, 256>>>(r1, wf1, bf1, o1, 256, 256, 1280);
    hgemm<0, true, false, float><<<gF, 256>>>(r2, wf2, bf2, o2, 256, 256, 1280);
    head_kernel<<<B_GR, 256>>>(o1, o2, fus, Wo1, bo1, Wo2, bo2, out);
}

// round 13
// speedup vs baseline: 1.3985x; 1.3985x over previous
#include <cuda_runtime.h>
#include <cuda_fp16.h>
#include <cstdint>
#include <cstddef>

#define B_GR 256
#define N_PG 64
#define D_DIM 256
#define T_TOT 16384
#define E_TOT 524288
#define E_PG 2048
#define BOND_D 16
#define SLOPE 0.22916666666666666f

// planes: index 0 = mol1, 1 = mol2
__device__ __half g_eb1[134217728];            // 256 MB fp16 edge bias mol1
__device__ __half g_eb2[134217728];            // 256 MB fp16 edge bias mol2
__device__ float g_yz[2ull * 8388608];         // [2][T][512]: y | z
__device__ float g_xm[2ull * 4194304];         // [2][T][256]
__device__ float g_wcat[2 * 131072];           // [2][256][512] = Wn | Ws
__device__ float g_wf[2 * 327680];             // [2] Wf, rows 256-511 x64
__device__ float g_r[2 * 327680];              // [2][B][1280]
__device__ float g_o[2 * 65536];               // [2][B][256]
__device__ float g_b0p[2 * 256];
__device__ float g_bmp[2 * 256];
__device__ float g_bfp[2 * 256];
__device__ float g_fus[B_GR * 6];
__device__ int g_ptr1[T_TOT + 1];
__device__ int g_ptr2[T_TOT + 1];
__device__ int2 g_pack1[E_TOT];
__device__ int2 g_pack2[E_TOT];
__device__ int g_is64[2];

// ---- 1: index dtype detection ----
__global__ void detect_kernel(const unsigned* e1, const unsigned* e2) {
    __shared__ int ok[2];
    int t = threadIdx.x;
    if (t < 2) ok[t] = 1;
    __syncthreads();
    if (e1[2 * t + 1]) ok[0] = 0;
    if (e2[2 * t + 1]) ok[1] = 0;
    __syncthreads();
    if (t < 2) g_is64[t] = ok[t];
}

__device__ __forceinline__ int loadIdx(const void* p, int is64, long long i) {
    return is64 ? (int)((const long long*)p)[i] : ((const int*)p)[i];
}

// ---- 2: merged per-graph CSR (blockIdx.y = molecule), stable order ----
__global__ void build_csr(const void* __restrict__ ei0, const void* __restrict__ ei1,
                          int* __restrict__ ptr0, int* __restrict__ ptr1,
                          int2* __restrict__ pack0, int2* __restrict__ pack1) {
    __shared__ int sl[E_PG], dl[E_PG], cnt[N_PG], base[N_PG];
    int g = blockIdx.x, t = threadIdx.x, which = blockIdx.y;
    const void* eidx = which ? ei1 : ei0;
    int* ptr = which ? ptr1 : ptr0;
    int2* pack = which ? pack1 : pack0;
    int is64 = g_is64[which];
    if (t < N_PG) cnt[t] = 0;
    __syncthreads();
    for (int e = t; e < E_PG; e += blockDim.x) {
        long long ge = (long long)g * E_PG + e;
        sl[e] = loadIdx(eidx, is64, ge) - g * N_PG;
        int d = loadIdx(eidx, is64, (long long)E_TOT + ge) - g * N_PG;
        dl[e] = d;
        atomicAdd(&cnt[d], 1);
    }
    __syncthreads();
    if (t == 0) {
        int run = 0;
        for (int n = 0; n < N_PG; n++) {
            base[n] = run;
            ptr[g * N_PG + n] = g * E_PG + run;
            run += cnt[n];
        }
        if (g == 0) ptr[T_TOT] = E_TOT;
    }
    __syncthreads();
    if (t < N_PG) {
        int p = g * E_PG + base[t];
        for (int e = 0; e < E_PG; e++)
            if (dl[e] == t) { pack[p] = make_int2((g * E_PG + e) * D_DIM, sl[e] * D_DIM); p++; }
    }
}

// ---- 3: single pack kernel: wcat both, wf both, bias packs ----
__global__ void pack_all(const float* Wn1, const float* Ws1, const float* Wn2, const float* Ws2,
                         const float* Wf1, const float* Wf2,
                         const float* b0_1, const float* b0_2,
                         const float* bm1, const float* bm2,
                         const float* bf1, const float* bf2,
                         float* wcat, float* wf, float* b0p, float* bmp, float* bfp) {
    int k = blockIdx.x, t = threadIdx.x;
    if (k < 256) {
        wcat[k * 512 + t] = Wn1[k * 256 + t];
        wcat[k * 512 + 256 + t] = Ws1[k * 256 + t];
        wcat[131072 + k * 512 + t] = Wn2[k * 256 + t];
        wcat[131072 + k * 512 + 256 + t] = Ws2[k * 256 + t];
        if (k == 0) { b0p[t] = b0_1[t]; bmp[t] = bm1[t]; bfp[t] = bf1[t]; }
        if (k == 1) { b0p[256 + t] = b0_2[t]; bmp[256 + t] = bm2[t]; bfp[256 + t] = bf2[t]; }
    } else {
        int kk = k - 256;
        float sc = (kk >= 256 && kk < 512) ? 64.f : 1.f;
        wf[kk * 256 + t] = Wf1[kk * 256 + t] * sc;
        wf[327680 + kk * 256 + t] = Wf2[kk * 256 + t] * sc;
    }
}

// ---- ptx helpers ----
__device__ __forceinline__ uint32_t su32(const void* p) {
    return (uint32_t)__cvta_generic_to_shared(p);
}
__device__ __forceinline__ void ldsm4(uint32_t* r, uint32_t addr) {
    asm volatile("ldmatrix.sync.aligned.m8n8.x4.shared.b16 {%0,%1,%2,%3}, [%4];"
                 : "=r"(r[0]), "=r"(r[1]), "=r"(r[2]), "=r"(r[3]) : "r"(addr));
}
__device__ __forceinline__ void ldsm4t(uint32_t* r, uint32_t addr) {
    asm volatile("ldmatrix.sync.aligned.m8n8.x4.trans.shared.b16 {%0,%1,%2,%3}, [%4];"
                 : "=r"(r[0]), "=r"(r[1]), "=r"(r[2]), "=r"(r[3]) : "r"(addr));
}
__device__ __forceinline__ void mma16816(float* c, const uint32_t* a, uint32_t b0, uint32_t b1) {
    asm volatile(
        "mma.sync.aligned.m16n8k16.row.col.f32.f16.f16.f32 "
        "{%0,%1,%2,%3},{%4,%5,%6,%7},{%8,%9},{%0,%1,%2,%3};"
        : "+f"(c[0]), "+f"(c[1]), "+f"(c[2]), "+f"(c[3])
        : "r"(a[0]), "r"(a[1]), "r"(a[2]), "r"(a[3]), "r"(b0), "r"(b1));
}

#define A_PAD 24
#define B_PAD 136

__device__ __forceinline__ void fill_tiles(__half* as_, __half* bs_,
                                           float4 a0, float4 a1, float4 b0, float4 b1,
                                           int arow, int ak, int bkr, int bcol) {
    __half2 h0 = __floats2half2_rn(a0.x, a0.y), h1 = __floats2half2_rn(a0.z, a0.w);
    __half2 h2 = __floats2half2_rn(a1.x, a1.y), h3 = __floats2half2_rn(a1.z, a1.w);
    uint4 u;
    u.x = *(uint32_t*)&h0; u.y = *(uint32_t*)&h1; u.z = *(uint32_t*)&h2; u.w = *(uint32_t*)&h3;
    *(uint4*)&as_[arow * A_PAD + ak] = u;
    __half2 p0 = __floats2half2_rn(b0.x, b0.y), p1 = __floats2half2_rn(b0.z, b0.w);
    uint2 v; v.x = *(uint32_t*)&p0; v.y = *(uint32_t*)&p1;
    *(uint2*)&bs_[bkr * B_PAD + bcol] = v;
    p0 = __floats2half2_rn(b1.x, b1.y); p1 = __floats2half2_rn(b1.z, b1.w);
    v.x = *(uint32_t*)&p0; v.y = *(uint32_t*)&p1;
    *(uint2*)&bs_[(bkr + 8) * B_PAD + bcol] = v;
}

// ---- fp32-in fp16-mma GEMM (round-8 proven core), molecule-merged via blockIdx.z ----
template <int ACT, typename OutT>
__global__ void __launch_bounds__(256) hgemm(const float* __restrict__ A0, const float* __restrict__ A1,
                                             const float* __restrict__ B0, const float* __restrict__ B1,
                                             const float* __restrict__ bias0, const float* __restrict__ bias1,
                                             OutT* __restrict__ C0, OutT* __restrict__ C1,
                                             int M, int N, int K) {
    __shared__ __align__(16) __half As[2][128 * A_PAD];
    __shared__ __align__(16) __half Bs[2][16 * B_PAD];
    int z = blockIdx.z;
    const float* A = z ? A1 : A0;
    const float* Bm = z ? B1 : B0;
    const float* bias = z ? bias1 : bias0;
    OutT* C = z ? C1 : C0;
    int tid = threadIdx.x;
    int wid = tid >> 5, lane = tid & 31;
    int gid = lane >> 2, tg = lane & 3;
    int row0 = blockIdx.y * 128, col0 = blockIdx.x * 128;
    int wrow = (wid & 3) * 32, wcol = (wid >> 2) * 64;
    int arow = tid >> 1, ak = (tid & 1) * 8;
    int bkr = tid >> 5, bcol = (tid & 31) * 4;
    const float* Ap = A + (size_t)(row0 + arow) * K + ak;
    const float* Bp0 = Bm + (size_t)bkr * N + col0 + bcol;
    const float* Bp1 = Bm + (size_t)(bkr + 8) * N + col0 + bcol;

    uint32_t aad[2][2], bad[2];
    {
        int arw = (lane & 15), acl = (lane >> 4) * 8;
        int bk = (lane & 7) + ((lane >> 4) & 1) * 8;
        int bn = wcol + ((lane >> 3) & 1) * 8;
#pragma unroll
        for (int b = 0; b < 2; b++) {
            aad[b][0] = su32(&As[b][(wrow + arw) * A_PAD + acl]);
            aad[b][1] = su32(&As[b][(wrow + 16 + arw) * A_PAD + acl]);
            bad[b] = su32(&Bs[b][bk * B_PAD + bn]);
        }
    }

    float acc[2][8][4];
#pragma unroll
    for (int i = 0; i < 2; i++)
#pragma unroll
        for (int j = 0; j < 8; j++)
#pragma unroll
            for (int q = 0; q < 4; q++) acc[i][j][q] = 0.f;

    {
        float4 a0 = *(const float4*)Ap;
        float4 a1 = *(const float4*)(Ap + 4);
        float4 b0 = *(const float4*)Bp0;
        float4 b1 = *(const float4*)Bp1;
        fill_tiles(As[0], Bs[0], a0, a1, b0, b1, arow, ak, bkr, bcol);
    }
    __syncthreads();

    int NT = K >> 4;
    int buf = 0;
    for (int kt = 0; kt < NT; kt++) {
        float4 pa0, pa1, pb0, pb1;
        if (kt + 1 < NT) {
            pa0 = *(const float4*)(Ap + (kt + 1) * 16);
            pa1 = *(const float4*)(Ap + (kt + 1) * 16 + 4);
            pb0 = *(const float4*)(Bp0 + (size_t)(kt + 1) * 16 * N);
            pb1 = *(const float4*)(Bp1 + (size_t)(kt + 1) * 16 * N);
        }
        uint32_t a[2][4], bf16[4][4];
        ldsm4(a[0], aad[buf][0]);
        ldsm4(a[1], aad[buf][1]);
#pragma unroll
        for (int jp = 0; jp < 4; jp++) ldsm4t(bf16[jp], bad[buf] + jp * 32);
#pragma unroll
        for (int i = 0; i < 2; i++)
#pragma unroll
            for (int j = 0; j < 8; j++)
                mma16816(acc[i][j], a[i], bf16[j >> 1][j & 1], bf16[j >> 1][2 + (j & 1)]);
        if (kt + 1 < NT) {
            buf ^= 1;
            fill_tiles(As[buf], Bs[buf], pa0, pa1, pb0, pb1, arow, ak, bkr, bcol);
            __syncthreads();
        }
    }

#pragma unroll
    for (int j = 0; j < 8; j++) {
        int c = col0 + wcol + j * 8 + tg * 2;
        float b0v = 0.f, b1v = 0.f;
        if (bias) { float2 bb = *(const float2*)(bias + c); b0v = bb.x; b1v = bb.y; }
#pragma unroll
        for (int i = 0; i < 2; i++) {
            int ra = row0 + wrow + i * 16 + gid;
            float v0 = acc[i][j][0] + b0v, v1 = acc[i][j][1] + b1v;
            float v2 = acc[i][j][2] + b0v, v3 = acc[i][j][3] + b1v;
            if (ACT == 2) {
                v0 = v0 >= 0.f ? v0 : SLOPE * v0; v1 = v1 >= 0.f ? v1 : SLOPE * v1;
                v2 = v2 >= 0.f ? v2 : SLOPE * v2; v3 = v3 >= 0.f ? v3 : SLOPE * v3;
            }
            if constexpr (sizeof(OutT) == 2) {
                *(__half2*)((__half*)C + (size_t)ra * N + c) = __floats2half2_rn(v0, v1);
                *(__half2*)((__half*)C + (size_t)(ra + 8) * N + c) = __floats2half2_rn(v2, v3);
            } else {
                *(float2*)((float*)C + (size_t)ra * N + c) = make_float2(v0, v1);
                *(float2*)((float*)C + (size_t)(ra + 8) * N + c) = make_float2(v2, v3);
            }
        }
    }
}

// ---- conv (round-8 core), molecule-merged via blockIdx.y ----
__global__ void conv_kernel(const float* __restrict__ yzb,
                            const __half* __restrict__ eb0, const __half* __restrict__ eb1,
                            const int* __restrict__ ptr0, const int* __restrict__ ptr1,
                            const int2* __restrict__ pack0, const int2* __restrict__ pack1,
                            const float* __restrict__ bs0, const float* __restrict__ bs1,
                            float* __restrict__ xmb) {
    extern __shared__ float ys[];
    int g = blockIdx.x, t = threadIdx.x, z = blockIdx.y;
    const __half* eb = z ? eb1 : eb0;
    const int* ptr = z ? ptr1 : ptr0;
    const int2* pack = z ? pack1 : pack0;
    const float* bs = z ? bs1 : bs0;
    const float* yg = yzb + (size_t)z * 8388608 + (size_t)g * N_PG * 512;
    float* xo = xmb + (size_t)z * 4194304;
    for (int i = t; i < N_PG * D_DIM; i += 256) {
        int n = i >> 8, d = i & 255;
        ys[i] = yg[n * 512 + d];
    }
    __syncthreads();
    int q = t >> 6, dd = (t & 63) * 4;
    float4 bsv = *(const float4*)(bs + dd);
    for (int n = q; n < N_PG; n += 4) {
        int p0 = ptr[g * N_PG + n], p1 = ptr[g * N_PG + n + 1];
        float ax = 0.f, ay = 0.f, az = 0.f, aw = 0.f;
#pragma unroll 2
        for (int j = p0; j < p1; j++) {
            int2 pr = pack[j];
            float4 yv = *(const float4*)(ys + pr.y + dd);
            uint2 raw = *(const uint2*)(eb + (size_t)pr.x + dd);
            float2 e0 = __half22float2(*(__half2*)&raw.x);
            float2 e1 = __half22float2(*(__half2*)&raw.y);
            ax += fmaxf(yv.x + e0.x, 0.f); ay += fmaxf(yv.y + e0.y, 0.f);
            az += fmaxf(yv.z + e1.x, 0.f); aw += fmaxf(yv.w + e1.y, 0.f);
        }
        float4 zv = *(const float4*)(yg + n * 512 + 256 + dd);
        size_t o = (size_t)(g * N_PG + n) * D_DIM + dd;
        float4 r;
        r.x = fmaxf(zv.x + ax + bsv.x, 0.f); r.y = fmaxf(zv.y + ay + bsv.y, 0.f);
        r.z = fmaxf(zv.z + az + bsv.z, 0.f); r.w = fmaxf(zv.w + aw + bsv.w, 0.f);
        *(float4*)(xo + o) = r;
    }
}

// ---- dot_pool via mma (fp32 in, x1/16 on fill — exact; result x256) ----
__global__ void __launch_bounds__(256) dotpool_kernel(const float* __restrict__ xmb,
                                                      float* __restrict__ fus, int s) {
    extern __shared__ __half sm_h[];
    __half* a = sm_h;            // [64][264]
    __half* b = sm_h + 64 * 264;
    __shared__ float rm[256], rs[256];
    int g = blockIdx.x, t = threadIdx.x;
    int wid = t >> 5, lane = t & 31;
    const float* p1 = xmb + (size_t)g * N_PG * D_DIM;
    const float* p2 = xmb + 4194304 + (size_t)g * N_PG * D_DIM;
    for (int i = t; i < 2048; i += 256) {
        int n = i >> 5, c = (i & 31) * 8;
        float4 u0 = *(const float4*)(p1 + (size_t)n * 256 + c);
        float4 u1 = *(const float4*)(p1 + (size_t)n * 256 + c + 4);
        __half2 h0 = __floats2half2_rn(u0.x * 0.0625f, u0.y * 0.0625f);
        __half2 h1 = __floats2half2_rn(u0.z * 0.0625f, u0.w * 0.0625f);
        __half2 h2 = __floats2half2_rn(u1.x * 0.0625f, u1.y * 0.0625f);
        __half2 h3 = __floats2half2_rn(u1.z * 0.0625f, u1.w * 0.0625f);
        uint4 uu; uu.x = *(uint32_t*)&h0; uu.y = *(uint32_t*)&h1; uu.z = *(uint32_t*)&h2; uu.w = *(uint32_t*)&h3;
        *(uint4*)&a[n * 264 + c] = uu;
        u0 = *(const float4*)(p2 + (size_t)n * 256 + c);
        u1 = *(const float4*)(p2 + (size_t)n * 256 + c + 4);
        h0 = __floats2half2_rn(u0.x * 0.0625f, u0.y * 0.0625f);
        h1 = __floats2half2_rn(u0.z * 0.0625f, u0.w * 0.0625f);
        h2 = __floats2half2_rn(u1.x * 0.0625f, u1.y * 0.0625f);
        h3 = __floats2half2_rn(u1.z * 0.0625f, u1.w * 0.0625f);
        uu.x = *(uint32_t*)&h0; uu.y = *(uint32_t*)&h1; uu.z = *(uint32_t*)&h2; uu.w = *(uint32_t*)&h3;
        *(uint4*)&b[n * 264 + c] = uu;
    }
    __syncthreads();
    int rt = (wid & 3) * 16, cb = (wid >> 2) * 32;
    uint32_t aaddr = su32(&a[(rt + (lane & 15)) * 264 + (lane >> 4) * 8]);
    uint32_t baddr0 = su32(&b[(cb + (lane & 7) + ((lane >> 4) & 1) * 8) * 264 + ((lane >> 3) & 1) * 8]);
    uint32_t baddr1 = baddr0 + 16 * 264 * 2;
    float acc[4][4];
#pragma unroll
    for (int i = 0; i < 4; i++)
#pragma unroll
        for (int j = 0; j < 4; j++) acc[i][j] = 0.f;
#pragma unroll
    for (int kk = 0; kk < 16; kk++) {
        uint32_t af[4], b0[4], b1[4];
        ldsm4(af, aaddr + kk * 32);
        ldsm4(b0, baddr0 + kk * 32);
        ldsm4(b1, baddr1 + kk * 32);
        mma16816(acc[0], af, b0[0], b0[1]);
        mma16816(acc[1], af, b0[2], b0[3]);
        mma16816(acc[2], af, b1[0], b1[1]);
        mma16816(acc[3], af, b1[2], b1[3]);
    }
    float lmax = -3.4e38f, ls = 0.f;
#pragma unroll
    for (int i = 0; i < 4; i++)
#pragma unroll
        for (int j = 0; j < 4; j++) { lmax = fmaxf(lmax, acc[i][j]); ls += acc[i][j]; }
    rm[t] = lmax; rs[t] = ls;
    __syncthreads();
    for (int o = 128; o > 0; o >>= 1) {
        if (t < o) { rm[t] = fmaxf(rm[t], rm[t + o]); rs[t] += rs[t + o]; }
        __syncthreads();
    }
    if (t == 0) {
        fus[g * 6 + 2 * s] = 256.f * rm[0];
        fus[g * 6 + 2 * s + 1] = 256.f * rs[0] / 4096.f;
    }
}

// ---- readout (round-8 core), merged via blockIdx.y ----
__global__ void readout_kernel(const float* __restrict__ xmb, float* __restrict__ rb) {
    __shared__ int ord[3];
    int g = blockIdx.x, t = threadIdx.x, z = blockIdx.y;
    const float* xg = xmb + (size_t)z * 4194304 + (size_t)g * N_PG * D_DIM;
    float* r = rb + (size_t)z * 327680;
    float s = 0.f;
    for (int n = 0; n < N_PG; n++) s += xg[n * D_DIM + t];
    r[g * 1280 + t] = s / 64.f;
    r[g * 1280 + 256 + t] = s / 64.f;   // sum as mean; Wf rows x64
    if (t < 32) {
        float v0 = xg[t * D_DIM + 255], v1 = xg[(t + 32) * D_DIM + 255];
        int i0 = t, i1 = t + 32;
        for (int k = 0; k < 3; k++) {
            float cv; int bi;
            if (v0 > v1 || (v0 == v1 && i0 < i1)) { cv = v0; bi = i0; } else { cv = v1; bi = i1; }
            for (int o = 16; o > 0; o >>= 1) {
                float ov = __shfl_down_sync(0xffffffffu, cv, o);
                int oi = __shfl_down_sync(0xffffffffu, bi, o);
                if (ov > cv || (ov == cv && oi < bi)) { cv = ov; bi = oi; }
            }
            bi = __shfl_sync(0xffffffffu, bi, 0);
            if (t == 0) ord[k] = bi;
            if (bi == i0) v0 = -3.4e38f;
            if (bi == i1) v1 = -3.4e38f;
        }
    }
    __syncthreads();
    for (int k = 0; k < 3; k++) r[g * 1280 + 512 + k * 256 + t] = xg[ord[k] * D_DIM + t];
}

// ---- head ----
__global__ void head_kernel(const float* __restrict__ ob,
                            const float* __restrict__ fus, const float* __restrict__ Wo1,
                            const float* __restrict__ bo1, const float* __restrict__ Wo2,
                            const float* __restrict__ bo2, float* __restrict__ out) {
    __shared__ float cat[518];
    __shared__ float r0[256], r1a[256];
    int g = blockIdx.x, t = threadIdx.x;
    cat[t] = ob[g * 256 + t];
    cat[256 + t] = ob[65536 + g * 256 + t];
    if (t < 6) cat[512 + t] = fus[g * 6 + t];
    __syncthreads();
    float h = bo1[t];
    for (int k = 0; k < 518; k++) h += cat[k] * Wo1[k * 256 + t];
    r0[t] = h * Wo2[t * 2];
    r1a[t] = h * Wo2[t * 2 + 1];
    __syncthreads();
    for (int o = 128; o > 0; o >>= 1) {
        if (t < o) { r0[t] += r0[t + o]; r1a[t] += r1a[t + o]; }
        __syncthreads();
    }
    if (t == 0) { out[g * 2] = r0[0] + bo2[0]; out[g * 2 + 1] = r1a[0] + bo2[1]; }
}

extern "C" void kernel_launch(void* const* d_in, const int* in_sizes, int n_in,
                              void* d_out, int out_size) {
    const float* x1 = (const float*)d_in[0];
    const void* ei1 = d_in[1];
    const float* ea1 = (const float*)d_in[2];
    const float* x2 = (const float*)d_in[4];
    const void* ei2 = d_in[5];
    const float* ea2 = (const float*)d_in[6];
    const float* W0_1 = (const float*)d_in[8];  const float* b0_1 = (const float*)d_in[9];
    const float* W0_2 = (const float*)d_in[10]; const float* b0_2 = (const float*)d_in[11];
    const float* Wn1 = (const float*)d_in[12];  const float* We1 = (const float*)d_in[13];
    const float* bm1 = (const float*)d_in[14];  const float* Ws1 = (const float*)d_in[15];
    const float* bs1 = (const float*)d_in[16];
    const float* Wn2 = (const float*)d_in[17];  const float* We2 = (const float*)d_in[18];
    const float* bm2 = (const float*)d_in[19];  const float* Ws2 = (const float*)d_in[20];
    const float* bs2 = (const float*)d_in[21];
    const float* Wf1 = (const float*)d_in[22];
    const float* Wf2 = (const float*)d_in[24];
    const float* Wo1 = (const float*)d_in[26];  const float* bo1 = (const float*)d_in[27];
    const float* Wo2 = (const float*)d_in[28];  const float* bo2 = (const float*)d_in[29];
    const float* bf1 = (const float*)d_in[23];
    const float* bf2 = (const float*)d_in[25];
    float* out = (float*)d_out;

    void* p;
    cudaGetSymbolAddress(&p, g_eb1);  __half* eb1 = (__half*)p;
    cudaGetSymbolAddress(&p, g_eb2);  __half* eb2 = (__half*)p;
    cudaGetSymbolAddress(&p, g_yz);   float* yz = (float*)p;
    cudaGetSymbolAddress(&p, g_xm);   float* xm = (float*)p;
    cudaGetSymbolAddress(&p, g_wcat); float* wc = (float*)p;
    cudaGetSymbolAddress(&p, g_wf);   float* wf = (float*)p;
    cudaGetSymbolAddress(&p, g_r);    float* r = (float*)p;
    cudaGetSymbolAddress(&p, g_o);    float* o = (float*)p;
    cudaGetSymbolAddress(&p, g_b0p);  float* b0p = (float*)p;
    cudaGetSymbolAddress(&p, g_bmp);  float* bmp = (float*)p;
    cudaGetSymbolAddress(&p, g_bfp);  float* bfp = (float*)p;
    cudaGetSymbolAddress(&p, g_fus);  float* fus = (float*)p;
    cudaGetSymbolAddress(&p, g_ptr1); int* ptr1 = (int*)p;
    cudaGetSymbolAddress(&p, g_ptr2); int* ptr2 = (int*)p;
    cudaGetSymbolAddress(&p, g_pack1); int2* pack1 = (int2*)p;
    cudaGetSymbolAddress(&p, g_pack2); int2* pack2 = (int2*)p;

    cudaFuncSetAttribute(conv_kernel, cudaFuncAttributeMaxDynamicSharedMemorySize, 65536);
    cudaFuncSetAttribute(dotpool_kernel, cudaFuncAttributeMaxDynamicSharedMemorySize, 2 * 64 * 264 * 2);

    // 1-3: setup (3 launches so ncu -s 5 lands on a heavy kernel)
    detect_kernel<<<1, 512>>>((const unsigned*)ei1, (const unsigned*)ei2);
    build_csr<<<dim3(B_GR, 2), 256>>>(ei1, ei2, ptr1, ptr2, pack1, pack2);
    pack_all<<<1536, 256>>>(Wn1, Ws1, Wn2, Ws2, Wf1, Wf2, b0_1, b0_2, bm1, bm2, bf1, bf2,
                            wc, wf, b0p, bmp, bfp);

    // 4: edge bias both mols: eb = ea @ We + bm (fp16 out)
    dim3 gE(2, E_TOT / 128, 2);
    hgemm<0, __half><<<gE, 256>>>(ea1, ea2, We1, We2, bmp, bmp + 256, eb1, eb2,
                                  E_TOT, 256, 16);

    // 5: input layer both mols
    dim3 gT(2, T_TOT / 128, 2);
    hgemm<2, float><<<gT, 256>>>(x1, x2, W0_1, W0_2, b0p, b0p + 256, xm, xm + 4194304,
                                 T_TOT, 256, 128);

    // loop: 6..14
    dim3 gYZ(4, T_TOT / 128, 2);   // N=512, both mols
    for (int s = 0; s < 3; s++) {
        hgemm<0, float><<<gYZ, 256>>>(xm, xm + 4194304, wc, wc + 131072, nullptr, nullptr,
                                      yz, yz + 8388608, T_TOT, 512, 256);
        conv_kernel<<<dim3(B_GR, 2), 256, 65536>>>(yz, eb1, eb2, ptr1, ptr2, pack1, pack2,
                                                   bs1, bs2, xm);
        dotpool_kernel<<<B_GR, 256, 2 * 64 * 264 * 2>>>(xm, fus, s);
    }

    // 15: readout both mols
    readout_kernel<<<dim3(B_GR, 2), 256>>>(xm, r);
    // 16: Wf both mols
    dim3 gF(2, 2, 2);
    hgemm<0, float><<<gF, 256>>>(r, r + 327680, wf, wf + 327680, bfp, bfp + 256,
                                 o, o + 65536, 256, 256, 1280);
    // 17: head
    head_kernel<<<B_GR, 256>>>(o, fus, Wo1, bo1, Wo2, bo2, out);
}

// round 14
// speedup vs baseline: 1.4052x; 1.0048x over previous
#include <cuda_runtime.h>
#include <cuda_fp16.h>
#include <cstdint>
#include <cstddef>

#define B_GR 256
#define N_PG 64
#define D_DIM 256
#define T_TOT 16384
#define E_TOT 524288
#define E_PG 2048
#define BOND_D 16
#define SLOPE 0.22916666666666666f

// planes: index 0 = mol1, 1 = mol2
__device__ __half g_eb1[134217728];            // 256 MB fp16 edge bias mol1
__device__ __half g_eb2[134217728];            // 256 MB fp16 edge bias mol2
__device__ float g_yz[2ull * 8388608];         // [2][T][512]: y | z
__device__ float g_xm[2ull * 4194304];         // [2][T][256]
__device__ float g_wcat[2 * 131072];           // [2][256][512] = Wn | Ws
__device__ float g_wf[2 * 327680];             // [2] Wf, rows 256-511 x64
__device__ float g_r[2 * 327680];              // [2][B][1280]
__device__ float g_o[2 * 65536];               // [2][B][256]
__device__ float g_b0p[2 * 256];
__device__ float g_bmp[2 * 256];
__device__ float g_bfp[2 * 256];
__device__ float g_fus[B_GR * 6];
__device__ int g_ptr1[T_TOT + 1];
__device__ int g_ptr2[T_TOT + 1];
__device__ int2 g_pack1[E_TOT];
__device__ int2 g_pack2[E_TOT];
__device__ int g_is64[2];

// ---- 1: index dtype detection ----
__global__ void detect_kernel(const unsigned* e1, const unsigned* e2) {
    __shared__ int ok[2];
    int t = threadIdx.x;
    if (t < 2) ok[t] = 1;
    __syncthreads();
    if (e1[2 * t + 1]) ok[0] = 0;
    if (e2[2 * t + 1]) ok[1] = 0;
    __syncthreads();
    if (t < 2) g_is64[t] = ok[t];
}

__device__ __forceinline__ int loadIdx(const void* p, int is64, long long i) {
    return is64 ? (int)((const long long*)p)[i] : ((const int*)p)[i];
}

// ---- 2: merged per-graph CSR (blockIdx.y = molecule), stable order ----
__global__ void build_csr(const void* __restrict__ ei0, const void* __restrict__ ei1,
                          int* __restrict__ ptr0, int* __restrict__ ptr1,
                          int2* __restrict__ pack0, int2* __restrict__ pack1) {
    __shared__ int sl[E_PG], dl[E_PG], cnt[N_PG], base[N_PG];
    int g = blockIdx.x, t = threadIdx.x, which = blockIdx.y;
    const void* eidx = which ? ei1 : ei0;
    int* ptr = which ? ptr1 : ptr0;
    int2* pack = which ? pack1 : pack0;
    int is64 = g_is64[which];
    if (t < N_PG) cnt[t] = 0;
    __syncthreads();
    for (int e = t; e < E_PG; e += blockDim.x) {
        long long ge = (long long)g * E_PG + e;
        sl[e] = loadIdx(eidx, is64, ge) - g * N_PG;
        int d = loadIdx(eidx, is64, (long long)E_TOT + ge) - g * N_PG;
        dl[e] = d;
        atomicAdd(&cnt[d], 1);
    }
    __syncthreads();
    if (t == 0) {
        int run = 0;
        for (int n = 0; n < N_PG; n++) {
            base[n] = run;
            ptr[g * N_PG + n] = g * E_PG + run;
            run += cnt[n];
        }
        if (g == 0) ptr[T_TOT] = E_TOT;
    }
    __syncthreads();
    if (t < N_PG) {
        int p = g * E_PG + base[t];
        for (int e = 0; e < E_PG; e++)
            if (dl[e] == t) { pack[p] = make_int2((g * E_PG + e) * D_DIM, sl[e] * D_DIM); p++; }
    }
}

// ---- 3: single pack kernel: wcat both, wf both, bias packs ----
__global__ void pack_all(const float* Wn1, const float* Ws1, const float* Wn2, const float* Ws2,
                         const float* Wf1, const float* Wf2,
                         const float* b0_1, const float* b0_2,
                         const float* bm1, const float* bm2,
                         const float* bf1, const float* bf2,
                         float* wcat, float* wf, float* b0p, float* bmp, float* bfp) {
    int k = blockIdx.x, t = threadIdx.x;
    if (k < 256) {
        wcat[k * 512 + t] = Wn1[k * 256 + t];
        wcat[k * 512 + 256 + t] = Ws1[k * 256 + t];
        wcat[131072 + k * 512 + t] = Wn2[k * 256 + t];
        wcat[131072 + k * 512 + 256 + t] = Ws2[k * 256 + t];
        if (k == 0) { b0p[t] = b0_1[t]; bmp[t] = bm1[t]; bfp[t] = bf1[t]; }
        if (k == 1) { b0p[256 + t] = b0_2[t]; bmp[256 + t] = bm2[t]; bfp[256 + t] = bf2[t]; }
    } else {
        int kk = k - 256;
        float sc = (kk >= 256 && kk < 512) ? 64.f : 1.f;
        wf[kk * 256 + t] = Wf1[kk * 256 + t] * sc;
        wf[327680 + kk * 256 + t] = Wf2[kk * 256 + t] * sc;
    }
}

// ---- ptx helpers ----
__device__ __forceinline__ uint32_t su32(const void* p) {
    return (uint32_t)__cvta_generic_to_shared(p);
}
__device__ __forceinline__ void ldsm4(uint32_t* r, uint32_t addr) {
    asm volatile("ldmatrix.sync.aligned.m8n8.x4.shared.b16 {%0,%1,%2,%3}, [%4];"
                 : "=r"(r[0]), "=r"(r[1]), "=r"(r[2]), "=r"(r[3]) : "r"(addr));
}
__device__ __forceinline__ void ldsm4t(uint32_t* r, uint32_t addr) {
    asm volatile("ldmatrix.sync.aligned.m8n8.x4.trans.shared.b16 {%0,%1,%2,%3}, [%4];"
                 : "=r"(r[0]), "=r"(r[1]), "=r"(r[2]), "=r"(r[3]) : "r"(addr));
}
__device__ __forceinline__ void mma16816(float* c, const uint32_t* a, uint32_t b0, uint32_t b1) {
    asm volatile(
        "mma.sync.aligned.m16n8k16.row.col.f32.f16.f16.f32 "
        "{%0,%1,%2,%3},{%4,%5,%6,%7},{%8,%9},{%0,%1,%2,%3};"
        : "+f"(c[0]), "+f"(c[1]), "+f"(c[2]), "+f"(c[3])
        : "r"(a[0]), "r"(a[1]), "r"(a[2]), "r"(a[3]), "r"(b0), "r"(b1));
}

#define A_PAD 24
#define B_PAD 136

__device__ __forceinline__ void fill_tiles(__half* as_, __half* bs_,
                                           float4 a0, float4 a1, float4 b0, float4 b1,
                                           int arow, int ak, int bkr, int bcol) {
    __half2 h0 = __floats2half2_rn(a0.x, a0.y), h1 = __floats2half2_rn(a0.z, a0.w);
    __half2 h2 = __floats2half2_rn(a1.x, a1.y), h3 = __floats2half2_rn(a1.z, a1.w);
    uint4 u;
    u.x = *(uint32_t*)&h0; u.y = *(uint32_t*)&h1; u.z = *(uint32_t*)&h2; u.w = *(uint32_t*)&h3;
    *(uint4*)&as_[arow * A_PAD + ak] = u;
    __half2 p0 = __floats2half2_rn(b0.x, b0.y), p1 = __floats2half2_rn(b0.z, b0.w);
    uint2 v; v.x = *(uint32_t*)&p0; v.y = *(uint32_t*)&p1;
    *(uint2*)&bs_[bkr * B_PAD + bcol] = v;
    p0 = __floats2half2_rn(b1.x, b1.y); p1 = __floats2half2_rn(b1.z, b1.w);
    v.x = *(uint32_t*)&p0; v.y = *(uint32_t*)&p1;
    *(uint2*)&bs_[(bkr + 8) * B_PAD + bcol] = v;
}

// ---- fp32-in fp16-mma GEMM, molecule-merged via blockIdx.z ----
// OutT==__half: SMEM-staged coalesced epilogue (uint4 stores).
template <int ACT, typename OutT>
__global__ void __launch_bounds__(256) hgemm(const float* __restrict__ A0, const float* __restrict__ A1,
                                             const float* __restrict__ B0, const float* __restrict__ B1,
                                             const float* __restrict__ bias0, const float* __restrict__ bias1,
                                             OutT* __restrict__ C0, OutT* __restrict__ C1,
                                             int M, int N, int K) {
    __shared__ __align__(16) __half As[2][128 * A_PAD];
    __shared__ __align__(16) __half Bs[2][16 * B_PAD];
    int z = blockIdx.z;
    const float* A = z ? A1 : A0;
    const float* Bm = z ? B1 : B0;
    const float* bias = z ? bias1 : bias0;
    OutT* C = z ? C1 : C0;
    int tid = threadIdx.x;
    int wid = tid >> 5, lane = tid & 31;
    int gid = lane >> 2, tg = lane & 3;
    int row0 = blockIdx.y * 128, col0 = blockIdx.x * 128;
    int wrow = (wid & 3) * 32, wcol = (wid >> 2) * 64;
    int arow = tid >> 1, ak = (tid & 1) * 8;
    int bkr = tid >> 5, bcol = (tid & 31) * 4;
    const float* Ap = A + (size_t)(row0 + arow) * K + ak;
    const float* Bp0 = Bm + (size_t)bkr * N + col0 + bcol;
    const float* Bp1 = Bm + (size_t)(bkr + 8) * N + col0 + bcol;

    uint32_t aad[2][2], bad[2];
    {
        int arw = (lane & 15), acl = (lane >> 4) * 8;
        int bk = (lane & 7) + ((lane >> 4) & 1) * 8;
        int bn = wcol + ((lane >> 3) & 1) * 8;
#pragma unroll
        for (int b = 0; b < 2; b++) {
            aad[b][0] = su32(&As[b][(wrow + arw) * A_PAD + acl]);
            aad[b][1] = su32(&As[b][(wrow + 16 + arw) * A_PAD + acl]);
            bad[b] = su32(&Bs[b][bk * B_PAD + bn]);
        }
    }

    float acc[2][8][4];
#pragma unroll
    for (int i = 0; i < 2; i++)
#pragma unroll
        for (int j = 0; j < 8; j++)
#pragma unroll
            for (int q = 0; q < 4; q++) acc[i][j][q] = 0.f;

    {
        float4 a0 = *(const float4*)Ap;
        float4 a1 = *(const float4*)(Ap + 4);
        float4 b0 = *(const float4*)Bp0;
        float4 b1 = *(const float4*)Bp1;
        fill_tiles(As[0], Bs[0], a0, a1, b0, b1, arow, ak, bkr, bcol);
    }
    __syncthreads();

    int NT = K >> 4;
    int buf = 0;
    for (int kt = 0; kt < NT; kt++) {
        float4 pa0, pa1, pb0, pb1;
        if (kt + 1 < NT) {
            pa0 = *(const float4*)(Ap + (kt + 1) * 16);
            pa1 = *(const float4*)(Ap + (kt + 1) * 16 + 4);
            pb0 = *(const float4*)(Bp0 + (size_t)(kt + 1) * 16 * N);
            pb1 = *(const float4*)(Bp1 + (size_t)(kt + 1) * 16 * N);
        }
        uint32_t a[2][4], bf16[4][4];
        ldsm4(a[0], aad[buf][0]);
        ldsm4(a[1], aad[buf][1]);
#pragma unroll
        for (int jp = 0; jp < 4; jp++) ldsm4t(bf16[jp], bad[buf] + jp * 32);
#pragma unroll
        for (int i = 0; i < 2; i++)
#pragma unroll
            for (int j = 0; j < 8; j++)
                mma16816(acc[i][j], a[i], bf16[j >> 1][j & 1], bf16[j >> 1][2 + (j & 1)]);
        if (kt + 1 < NT) {
            buf ^= 1;
            fill_tiles(As[buf], Bs[buf], pa0, pa1, pb0, pb1, arow, ak, bkr, bcol);
            __syncthreads();
        }
    }

    if constexpr (sizeof(OutT) == 2) {
        // staged coalesced fp16 epilogue: two 64-row chunks through SMEM
        __shared__ __align__(16) __half St[64 * 136];
        __syncthreads();
#pragma unroll
        for (int ch = 0; ch < 2; ch++) {
            if (((wid & 3) >> 1) == ch) {
                int wrl = ((wid & 3) & 1) * 32;
#pragma unroll
                for (int j = 0; j < 8; j++) {
                    int cc = wcol + j * 8 + tg * 2;
                    float b0v = 0.f, b1v = 0.f;
                    if (bias) { float2 bb = *(const float2*)(bias + col0 + cc); b0v = bb.x; b1v = bb.y; }
#pragma unroll
                    for (int i = 0; i < 2; i++) {
                        int lr = wrl + i * 16 + gid;
                        float v0 = acc[i][j][0] + b0v, v1 = acc[i][j][1] + b1v;
                        float v2 = acc[i][j][2] + b0v, v3 = acc[i][j][3] + b1v;
                        if (ACT == 2) {
                            v0 = v0 >= 0.f ? v0 : SLOPE * v0; v1 = v1 >= 0.f ? v1 : SLOPE * v1;
                            v2 = v2 >= 0.f ? v2 : SLOPE * v2; v3 = v3 >= 0.f ? v3 : SLOPE * v3;
                        }
                        *(__half2*)&St[lr * 136 + cc] = __floats2half2_rn(v0, v1);
                        *(__half2*)&St[(lr + 8) * 136 + cc] = __floats2half2_rn(v2, v3);
                    }
                }
            }
            __syncthreads();
#pragma unroll
            for (int u = 0; u < 4; u++) {
                int q = tid + 256 * u;           // 0..1023
                int lr = q >> 4, cc = (q & 15) * 8;
                uint4 val = *(uint4*)&St[lr * 136 + cc];
                *(uint4*)((__half*)C + (size_t)(row0 + ch * 64 + lr) * N + col0 + cc) = val;
            }
            __syncthreads();
        }
    } else {
#pragma unroll
        for (int j = 0; j < 8; j++) {
            int c = col0 + wcol + j * 8 + tg * 2;
            float b0v = 0.f, b1v = 0.f;
            if (bias) { float2 bb = *(const float2*)(bias + c); b0v = bb.x; b1v = bb.y; }
#pragma unroll
            for (int i = 0; i < 2; i++) {
                int ra = row0 + wrow + i * 16 + gid;
                float v0 = acc[i][j][0] + b0v, v1 = acc[i][j][1] + b1v;
                float v2 = acc[i][j][2] + b0v, v3 = acc[i][j][3] + b1v;
                if (ACT == 2) {
                    v0 = v0 >= 0.f ? v0 : SLOPE * v0; v1 = v1 >= 0.f ? v1 : SLOPE * v1;
                    v2 = v2 >= 0.f ? v2 : SLOPE * v2; v3 = v3 >= 0.f ? v3 : SLOPE * v3;
                }
                *(float2*)((float*)C + (size_t)ra * N + c) = make_float2(v0, v1);
                *(float2*)((float*)C + (size_t)(ra + 8) * N + c) = make_float2(v2, v3);
            }
        }
    }
}

// ---- conv, molecule-merged via blockIdx.y ----
__global__ void conv_kernel(const float* __restrict__ yzb,
                            const __half* __restrict__ eb0, const __half* __restrict__ eb1,
                            const int* __restrict__ ptr0, const int* __restrict__ ptr1,
                            const int2* __restrict__ pack0, const int2* __restrict__ pack1,
                            const float* __restrict__ bs0, const float* __restrict__ bs1,
                            float* __restrict__ xmb) {
    extern __shared__ float ys[];
    int g = blockIdx.x, t = threadIdx.x, z = blockIdx.y;
    const __half* eb = z ? eb1 : eb0;
    const int* ptr = z ? ptr1 : ptr0;
    const int2* pack = z ? pack1 : pack0;
    const float* bs = z ? bs1 : bs0;
    const float* yg = yzb + (size_t)z * 8388608 + (size_t)g * N_PG * 512;
    float* xo = xmb + (size_t)z * 4194304;
    for (int i = t; i < N_PG * D_DIM; i += 256) {
        int n = i >> 8, d = i & 255;
        ys[i] = yg[n * 512 + d];
    }
    __syncthreads();
    int q = t >> 6, dd = (t & 63) * 4;
    float4 bsv = *(const float4*)(bs + dd);
    for (int n = q; n < N_PG; n += 4) {
        int p0 = ptr[g * N_PG + n], p1 = ptr[g * N_PG + n + 1];
        float ax = 0.f, ay = 0.f, az = 0.f, aw = 0.f;
#pragma unroll 2
        for (int j = p0; j < p1; j++) {
            int2 pr = pack[j];
            float4 yv = *(const float4*)(ys + pr.y + dd);
            uint2 raw = *(const uint2*)(eb + (size_t)pr.x + dd);
            float2 e0 = __half22float2(*(__half2*)&raw.x);
            float2 e1 = __half22float2(*(__half2*)&raw.y);
            ax += fmaxf(yv.x + e0.x, 0.f); ay += fmaxf(yv.y + e0.y, 0.f);
            az += fmaxf(yv.z + e1.x, 0.f); aw += fmaxf(yv.w + e1.y, 0.f);
        }
        float4 zv = *(const float4*)(yg + n * 512 + 256 + dd);
        size_t o = (size_t)(g * N_PG + n) * D_DIM + dd;
        float4 r;
        r.x = fmaxf(zv.x + ax + bsv.x, 0.f); r.y = fmaxf(zv.y + ay + bsv.y, 0.f);
        r.z = fmaxf(zv.z + az + bsv.z, 0.f); r.w = fmaxf(zv.w + aw + bsv.w, 0.f);
        *(float4*)(xo + o) = r;
    }
}

// ---- dot_pool via mma (fp32 in, x1/16 on fill — exact; result x256) ----
__global__ void __launch_bounds__(256) dotpool_kernel(const float* __restrict__ xmb,
                                                      float* __restrict__ fus, int s) {
    extern __shared__ __half sm_h[];
    __half* a = sm_h;            // [64][264]
    __half* b = sm_h + 64 * 264;
    __shared__ float rm[256], rs[256];
    int g = blockIdx.x, t = threadIdx.x;
    int wid = t >> 5, lane = t & 31;
    const float* p1 = xmb + (size_t)g * N_PG * D_DIM;
    const float* p2 = xmb + 4194304 + (size_t)g * N_PG * D_DIM;
    for (int i = t; i < 2048; i += 256) {
        int n = i >> 5, c = (i & 31) * 8;
        float4 u0 = *(const float4*)(p1 + (size_t)n * 256 + c);
        float4 u1 = *(const float4*)(p1 + (size_t)n * 256 + c + 4);
        __half2 h0 = __floats2half2_rn(u0.x * 0.0625f, u0.y * 0.0625f);
        __half2 h1 = __floats2half2_rn(u0.z * 0.0625f, u0.w * 0.0625f);
        __half2 h2 = __floats2half2_rn(u1.x * 0.0625f, u1.y * 0.0625f);
        __half2 h3 = __floats2half2_rn(u1.z * 0.0625f, u1.w * 0.0625f);
        uint4 uu; uu.x = *(uint32_t*)&h0; uu.y = *(uint32_t*)&h1; uu.z = *(uint32_t*)&h2; uu.w = *(uint32_t*)&h3;
        *(uint4*)&a[n * 264 + c] = uu;
        u0 = *(const float4*)(p2 + (size_t)n * 256 + c);
        u1 = *(const float4*)(p2 + (size_t)n * 256 + c + 4);
        h0 = __floats2half2_rn(u0.x * 0.0625f, u0.y * 0.0625f);
        h1 = __floats2half2_rn(u0.z * 0.0625f, u0.w * 0.0625f);
        h2 = __floats2half2_rn(u1.x * 0.0625f, u1.y * 0.0625f);
        h3 = __floats2half2_rn(u1.z * 0.0625f, u1.w * 0.0625f);
        uu.x = *(uint32_t*)&h0; uu.y = *(uint32_t*)&h1; uu.z = *(uint32_t*)&h2; uu.w = *(uint32_t*)&h3;
        *(uint4*)&b[n * 264 + c] = uu;
    }
    __syncthreads();
    int rt = (wid & 3) * 16, cb = (wid >> 2) * 32;
    uint32_t aaddr = su32(&a[(rt + (lane & 15)) * 264 + (lane >> 4) * 8]);
    uint32_t baddr0 = su32(&b[(cb + (lane & 7) + ((lane >> 4) & 1) * 8) * 264 + ((lane >> 3) & 1) * 8]);
    uint32_t baddr1 = baddr0 + 16 * 264 * 2;
    float acc[4][4];
#pragma unroll
    for (int i = 0; i < 4; i++)
#pragma unroll
        for (int j = 0; j < 4; j++) acc[i][j] = 0.f;
#pragma unroll
    for (int kk = 0; kk < 16; kk++) {
        uint32_t af[4], b0[4], b1[4];
        ldsm4(af, aaddr + kk * 32);
        ldsm4(b0, baddr0 + kk * 32);
        ldsm4(b1, baddr1 + kk * 32);
        mma16816(acc[0], af, b0[0], b0[1]);
        mma16816(acc[1], af, b0[2], b0[3]);
        mma16816(acc[2], af, b1[0], b1[1]);
        mma16816(acc[3], af, b1[2], b1[3]);
    }
    float lmax = -3.4e38f, ls = 0.f;
#pragma unroll
    for (int i = 0; i < 4; i++)
#pragma unroll
        for (int j = 0; j < 4; j++) { lmax = fmaxf(lmax, acc[i][j]); ls += acc[i][j]; }
    rm[t] = lmax; rs[t] = ls;
    __syncthreads();
    for (int o = 128; o > 0; o >>= 1) {
        if (t < o) { rm[t] = fmaxf(rm[t], rm[t + o]); rs[t] += rs[t + o]; }
        __syncthreads();
    }
    if (t == 0) {
        fus[g * 6 + 2 * s] = 256.f * rm[0];
        fus[g * 6 + 2 * s + 1] = 256.f * rs[0] / 4096.f;
    }
}

// ---- readout, merged via blockIdx.y ----
__global__ void readout_kernel(const float* __restrict__ xmb, float* __restrict__ rb) {
    __shared__ int ord[3];
    int g = blockIdx.x, t = threadIdx.x, z = blockIdx.y;
    const float* xg = xmb + (size_t)z * 4194304 + (size_t)g * N_PG * D_DIM;
    float* r = rb + (size_t)z * 327680;
    float s = 0.f;
    for (int n = 0; n < N_PG; n++) s += xg[n * D_DIM + t];
    r[g * 1280 + t] = s / 64.f;
    r[g * 1280 + 256 + t] = s / 64.f;   // sum as mean; Wf rows x64
    if (t < 32) {
        float v0 = xg[t * D_DIM + 255], v1 = xg[(t + 32) * D_DIM + 255];
        int i0 = t, i1 = t + 32;
        for (int k = 0; k < 3; k++) {
            float cv; int bi;
            if (v0 > v1 || (v0 == v1 && i0 < i1)) { cv = v0; bi = i0; } else { cv = v1; bi = i1; }
            for (int o = 16; o > 0; o >>= 1) {
                float ov = __shfl_down_sync(0xffffffffu, cv, o);
                int oi = __shfl_down_sync(0xffffffffu, bi, o);
                if (ov > cv || (ov == cv && oi < bi)) { cv = ov; bi = oi; }
            }
            bi = __shfl_sync(0xffffffffu, bi, 0);
            if (t == 0) ord[k] = bi;
            if (bi == i0) v0 = -3.4e38f;
            if (bi == i1) v1 = -3.4e38f;
        }
    }
    __syncthreads();
    for (int k = 0; k < 3; k++) r[g * 1280 + 512 + k * 256 + t] = xg[ord[k] * D_DIM + t];
}

// ---- head ----
__global__ void head_kernel(const float* __restrict__ ob,
                            const float* __restrict__ fus, const float* __restrict__ Wo1,
                            const float* __restrict__ bo1, const float* __restrict__ Wo2,
                            const float* __restrict__ bo2, float* __restrict__ out) {
    __shared__ float cat[518];
    __shared__ float r0[256], r1a[256];
    int g = blockIdx.x, t = threadIdx.x;
    cat[t] = ob[g * 256 + t];
    cat[256 + t] = ob[65536 + g * 256 + t];
    if (t < 6) cat[512 + t] = fus[g * 6 + t];
    __syncthreads();
    float h = bo1[t];
    for (int k = 0; k < 518; k++) h += cat[k] * Wo1[k * 256 + t];
    r0[t] = h * Wo2[t * 2];
    r1a[t] = h * Wo2[t * 2 + 1];
    __syncthreads();
    for (int o = 128; o > 0; o >>= 1) {
        if (t < o) { r0[t] += r0[t + o]; r1a[t] += r1a[t + o]; }
        __syncthreads();
    }
    if (t == 0) { out[g * 2] = r0[0] + bo2[0]; out[g * 2 + 1] = r1a[0] + bo2[1]; }
}

extern "C" void kernel_launch(void* const* d_in, const int* in_sizes, int n_in,
                              void* d_out, int out_size) {
    const float* x1 = (const float*)d_in[0];
    const void* ei1 = d_in[1];
    const float* ea1 = (const float*)d_in[2];
    const float* x2 = (const float*)d_in[4];
    const void* ei2 = d_in[5];
    const float* ea2 = (const float*)d_in[6];
    const float* W0_1 = (const float*)d_in[8];  const float* b0_1 = (const float*)d_in[9];
    const float* W0_2 = (const float*)d_in[10]; const float* b0_2 = (const float*)d_in[11];
    const float* Wn1 = (const float*)d_in[12];  const float* We1 = (const float*)d_in[13];
    const float* bm1 = (const float*)d_in[14];  const float* Ws1 = (const float*)d_in[15];
    const float* bs1 = (const float*)d_in[16];
    const float* Wn2 = (const float*)d_in[17];  const float* We2 = (const float*)d_in[18];
    const float* bm2 = (const float*)d_in[19];  const float* Ws2 = (const float*)d_in[20];
    const float* bs2 = (const float*)d_in[21];
    const float* Wf1 = (const float*)d_in[22];  const float* bf1 = (const float*)d_in[23];
    const float* Wf2 = (const float*)d_in[24];  const float* bf2 = (const float*)d_in[25];
    const float* Wo1 = (const float*)d_in[26];  const float* bo1 = (const float*)d_in[27];
    const float* Wo2 = (const float*)d_in[28];  const float* bo2 = (const float*)d_in[29];
    float* out = (float*)d_out;

    void* p;
    cudaGetSymbolAddress(&p, g_eb1);  __half* eb1 = (__half*)p;
    cudaGetSymbolAddress(&p, g_eb2);  __half* eb2 = (__half*)p;
    cudaGetSymbolAddress(&p, g_yz);   float* yz = (float*)p;
    cudaGetSymbolAddress(&p, g_xm);   float* xm = (float*)p;
    cudaGetSymbolAddress(&p, g_wcat); float* wc = (float*)p;
    cudaGetSymbolAddress(&p, g_wf);   float* wf = (float*)p;
    cudaGetSymbolAddress(&p, g_r);    float* r = (float*)p;
    cudaGetSymbolAddress(&p, g_o);    float* o = (float*)p;
    cudaGetSymbolAddress(&p, g_b0p);  float* b0p = (float*)p;
    cudaGetSymbolAddress(&p, g_bmp);  float* bmp = (float*)p;
    cudaGetSymbolAddress(&p, g_bfp);  float* bfp = (float*)p;
    cudaGetSymbolAddress(&p, g_fus);  float* fus = (float*)p;
    cudaGetSymbolAddress(&p, g_ptr1); int* ptr1 = (int*)p;
    cudaGetSymbolAddress(&p, g_ptr2); int* ptr2 = (int*)p;
    cudaGetSymbolAddress(&p, g_pack1); int2* pack1 = (int2*)p;
    cudaGetSymbolAddress(&p, g_pack2); int2* pack2 = (int2*)p;

    cudaFuncSetAttribute(conv_kernel, cudaFuncAttributeMaxDynamicSharedMemorySize, 65536);
    cudaFuncSetAttribute(dotpool_kernel, cudaFuncAttributeMaxDynamicSharedMemorySize, 2 * 64 * 264 * 2);

    // 1-3: setup
    detect_kernel<<<1, 512>>>((const unsigned*)ei1, (const unsigned*)ei2);
    build_csr<<<dim3(B_GR, 2), 256>>>(ei1, ei2, ptr1, ptr2, pack1, pack2);
    pack_all<<<1536, 256>>>(Wn1, Ws1, Wn2, Ws2, Wf1, Wf2, b0_1, b0_2, bm1, bm2, bf1, bf2,
                            wc, wf, b0p, bmp, bfp);

    // 4: edge bias both mols: eb = ea @ We + bm (fp16 out, staged epilogue)
    dim3 gE(2, E_TOT / 128, 2);
    hgemm<0, __half><<<gE, 256>>>(ea1, ea2, We1, We2, bmp, bmp + 256, eb1, eb2,
                                  E_TOT, 256, 16);

    // 5: input layer both mols
    dim3 gT(2, T_TOT / 128, 2);
    hgemm<2, float><<<gT, 256>>>(x1, x2, W0_1, W0_2, b0p, b0p + 256, xm, xm + 4194304,
                                 T_TOT, 256, 128);

    // loop
    dim3 gYZ(4, T_TOT / 128, 2);   // N=512, both mols
    for (int s = 0; s < 3; s++) {
        hgemm<0, float><<<gYZ, 256>>>(xm, xm + 4194304, wc, wc + 131072, nullptr, nullptr,
                                      yz, yz + 8388608, T_TOT, 512, 256);
        conv_kernel<<<dim3(B_GR, 2), 256, 65536>>>(yz, eb1, eb2, ptr1, ptr2, pack1, pack2,
                                                   bs1, bs2, xm);
        dotpool_kernel<<<B_GR, 256, 2 * 64 * 264 * 2>>>(xm, fus, s);
    }

    // readout / Wf / head
    readout_kernel<<<dim3(B_GR, 2), 256>>>(xm, r);
    dim3 gF(2, 2, 2);
    hgemm<0, float><<<gF, 256>>>(r, r + 327680, wf, wf + 327680, bfp, bfp + 256,
                                 o, o + 65536, 256, 256, 1280);
    head_kernel<<<B_GR, 256>>>(o, fus, Wo1, bo1, Wo2, bo2, out);
}

// round 16
// speedup vs baseline: 1.5026x; 1.0692x over previous
#include <cuda_runtime.h>
#include <cuda_fp16.h>
#include <cstdint>
#include <cstddef>

#define B_GR 256
#define N_PG 64
#define D_DIM 256
#define T_TOT 16384
#define E_TOT 524288
#define E_PG 2048
#define BOND_D 16
#define SLOPE 0.22916666666666666f

// planes: index 0 = mol1, 1 = mol2
__device__ float g_yz[2ull * 8388608];         // [2][T][512]: y | z
__device__ float g_xm[2ull * 4194304];         // [2][T][256]
__device__ float g_wcat[2 * 131072];           // [2][256][512] = Wn | Ws
__device__ float g_wf[2 * 327680];             // [2] Wf, rows 256-511 x64
__device__ float g_r[2 * 327680];              // [2][B][1280]
__device__ float g_o[2 * 65536];               // [2][B][256]
__device__ float g_b0p[2 * 256];
__device__ float g_bmp[2 * 256];
__device__ float g_bfp[2 * 256];
__device__ float g_fus[B_GR * 6];
__device__ int g_ptr1[T_TOT + 1];
__device__ int g_ptr2[T_TOT + 1];
__device__ int2 g_pack1[E_TOT];                // (global edge id, src_local)
__device__ int2 g_pack2[E_TOT];
__device__ int g_is64[2];

// ---- 1: index dtype detection ----
__global__ void detect_kernel(const unsigned* e1, const unsigned* e2) {
    __shared__ int ok[2];
    int t = threadIdx.x;
    if (t < 2) ok[t] = 1;
    __syncthreads();
    if (e1[2 * t + 1]) ok[0] = 0;
    if (e2[2 * t + 1]) ok[1] = 0;
    __syncthreads();
    if (t < 2) g_is64[t] = ok[t];
}

__device__ __forceinline__ int loadIdx(const void* p, int is64, long long i) {
    return is64 ? (int)((const long long*)p)[i] : ((const int*)p)[i];
}

// ---- 2: merged per-graph CSR (blockIdx.y = molecule), stable order ----
__global__ void build_csr(const void* __restrict__ ei0, const void* __restrict__ ei1,
                          int* __restrict__ ptr0, int* __restrict__ ptr1,
                          int2* __restrict__ pack0, int2* __restrict__ pack1) {
    __shared__ int sl[E_PG], dl[E_PG], cnt[N_PG], base[N_PG];
    int g = blockIdx.x, t = threadIdx.x, which = blockIdx.y;
    const void* eidx = which ? ei1 : ei0;
    int* ptr = which ? ptr1 : ptr0;
    int2* pack = which ? pack1 : pack0;
    int is64 = g_is64[which];
    if (t < N_PG) cnt[t] = 0;
    __syncthreads();
    for (int e = t; e < E_PG; e += blockDim.x) {
        long long ge = (long long)g * E_PG + e;
        sl[e] = loadIdx(eidx, is64, ge) - g * N_PG;
        int d = loadIdx(eidx, is64, (long long)E_TOT + ge) - g * N_PG;
        dl[e] = d;
        atomicAdd(&cnt[d], 1);
    }
    __syncthreads();
    if (t == 0) {
        int run = 0;
        for (int n = 0; n < N_PG; n++) {
            base[n] = run;
            ptr[g * N_PG + n] = g * E_PG + run;
            run += cnt[n];
        }
        if (g == 0) ptr[T_TOT] = E_TOT;
    }
    __syncthreads();
    if (t < N_PG) {
        int p = g * E_PG + base[t];
        for (int e = 0; e < E_PG; e++)
            if (dl[e] == t) { pack[p] = make_int2(g * E_PG + e, sl[e]); p++; }
    }
}

// ---- 3: single pack kernel ----
__global__ void pack_all(const float* Wn1, const float* Ws1, const float* Wn2, const float* Ws2,
                         const float* Wf1, const float* Wf2,
                         const float* b0_1, const float* b0_2,
                         const float* bm1, const float* bm2,
                         const float* bf1, const float* bf2,
                         float* wcat, float* wf, float* b0p, float* bmp, float* bfp) {
    int k = blockIdx.x, t = threadIdx.x;
    if (k < 256) {
        wcat[k * 512 + t] = Wn1[k * 256 + t];
        wcat[k * 512 + 256 + t] = Ws1[k * 256 + t];
        wcat[131072 + k * 512 + t] = Wn2[k * 256 + t];
        wcat[131072 + k * 512 + 256 + t] = Ws2[k * 256 + t];
        if (k == 0) { b0p[t] = b0_1[t]; bmp[t] = bm1[t]; bfp[t] = bf1[t]; }
        if (k == 1) { b0p[256 + t] = b0_2[t]; bmp[256 + t] = bm2[t]; bfp[256 + t] = bf2[t]; }
    } else {
        int kk = k - 256;
        float sc = (kk >= 256 && kk < 512) ? 64.f : 1.f;
        wf[kk * 256 + t] = Wf1[kk * 256 + t] * sc;
        wf[327680 + kk * 256 + t] = Wf2[kk * 256 + t] * sc;
    }
}

// ---- ptx helpers ----
__device__ __forceinline__ uint32_t su32(const void* p) {
    return (uint32_t)__cvta_generic_to_shared(p);
}
__device__ __forceinline__ void ldsm4(uint32_t* r, uint32_t addr) {
    asm volatile("ldmatrix.sync.aligned.m8n8.x4.shared.b16 {%0,%1,%2,%3}, [%4];"
                 : "=r"(r[0]), "=r"(r[1]), "=r"(r[2]), "=r"(r[3]) : "r"(addr));
}
__device__ __forceinline__ void ldsm4t(uint32_t* r, uint32_t addr) {
    asm volatile("ldmatrix.sync.aligned.m8n8.x4.trans.shared.b16 {%0,%1,%2,%3}, [%4];"
                 : "=r"(r[0]), "=r"(r[1]), "=r"(r[2]), "=r"(r[3]) : "r"(addr));
}
__device__ __forceinline__ void mma16816(float* c, const uint32_t* a, uint32_t b0, uint32_t b1) {
    asm volatile(
        "mma.sync.aligned.m16n8k16.row.col.f32.f16.f16.f32 "
        "{%0,%1,%2,%3},{%4,%5,%6,%7},{%8,%9},{%0,%1,%2,%3};"
        : "+f"(c[0]), "+f"(c[1]), "+f"(c[2]), "+f"(c[3])
        : "r"(a[0]), "r"(a[1]), "r"(a[2]), "r"(a[3]), "r"(b0), "r"(b1));
}

#define A_PAD 24
#define B_PAD 136

__device__ __forceinline__ void fill_tiles(__half* as_, __half* bs_,
                                           float4 a0, float4 a1, float4 b0, float4 b1,
                                           int arow, int ak, int bkr, int bcol) {
    __half2 h0 = __floats2half2_rn(a0.x, a0.y), h1 = __floats2half2_rn(a0.z, a0.w);
    __half2 h2 = __floats2half2_rn(a1.x, a1.y), h3 = __floats2half2_rn(a1.z, a1.w);
    uint4 u;
    u.x = *(uint32_t*)&h0; u.y = *(uint32_t*)&h1; u.z = *(uint32_t*)&h2; u.w = *(uint32_t*)&h3;
    *(uint4*)&as_[arow * A_PAD + ak] = u;
    __half2 p0 = __floats2half2_rn(b0.x, b0.y), p1 = __floats2half2_rn(b0.z, b0.w);
    uint2 v; v.x = *(uint32_t*)&p0; v.y = *(uint32_t*)&p1;
    *(uint2*)&bs_[bkr * B_PAD + bcol] = v;
    p0 = __floats2half2_rn(b1.x, b1.y); p1 = __floats2half2_rn(b1.z, b1.w);
    v.x = *(uint32_t*)&p0; v.y = *(uint32_t*)&p1;
    *(uint2*)&bs_[(bkr + 8) * B_PAD + bcol] = v;
}

// ---- fp32-in fp16-mma GEMM, molecule-merged via blockIdx.z ----
template <int ACT, typename OutT>
__global__ void __launch_bounds__(256) hgemm(const float* __restrict__ A0, const float* __restrict__ A1,
                                             const float* __restrict__ B0, const float* __restrict__ B1,
                                             const float* __restrict__ bias0, const float* __restrict__ bias1,
                                             OutT* __restrict__ C0, OutT* __restrict__ C1,
                                             int M, int N, int K) {
    __shared__ __align__(16) __half As[2][128 * A_PAD];
    __shared__ __align__(16) __half Bs[2][16 * B_PAD];
    int z = blockIdx.z;
    const float* A = z ? A1 : A0;
    const float* Bm = z ? B1 : B0;
    const float* bias = z ? bias1 : bias0;
    OutT* C = z ? C1 : C0;
    int tid = threadIdx.x;
    int wid = tid >> 5, lane = tid & 31;
    int gid = lane >> 2, tg = lane & 3;
    int row0 = blockIdx.y * 128, col0 = blockIdx.x * 128;
    int wrow = (wid & 3) * 32, wcol = (wid >> 2) * 64;
    int arow = tid >> 1, ak = (tid & 1) * 8;
    int bkr = tid >> 5, bcol = (tid & 31) * 4;
    const float* Ap = A + (size_t)(row0 + arow) * K + ak;
    const float* Bp0 = Bm + (size_t)bkr * N + col0 + bcol;
    const float* Bp1 = Bm + (size_t)(bkr + 8) * N + col0 + bcol;

    uint32_t aad[2][2], bad[2];
    {
        int arw = (lane & 15), acl = (lane >> 4) * 8;
        int bk = (lane & 7) + ((lane >> 4) & 1) * 8;
        int bn = wcol + ((lane >> 3) & 1) * 8;
#pragma unroll
        for (int b = 0; b < 2; b++) {
            aad[b][0] = su32(&As[b][(wrow + arw) * A_PAD + acl]);
            aad[b][1] = su32(&As[b][(wrow + 16 + arw) * A_PAD + acl]);
            bad[b] = su32(&Bs[b][bk * B_PAD + bn]);
        }
    }

    float acc[2][8][4];
#pragma unroll
    for (int i = 0; i < 2; i++)
#pragma unroll
        for (int j = 0; j < 8; j++)
#pragma unroll
            for (int q = 0; q < 4; q++) acc[i][j][q] = 0.f;

    {
        float4 a0 = *(const float4*)Ap;
        float4 a1 = *(const float4*)(Ap + 4);
        float4 b0 = *(const float4*)Bp0;
        float4 b1 = *(const float4*)Bp1;
        fill_tiles(As[0], Bs[0], a0, a1, b0, b1, arow, ak, bkr, bcol);
    }
    __syncthreads();

    int NT = K >> 4;
    int buf = 0;
    for (int kt = 0; kt < NT; kt++) {
        float4 pa0, pa1, pb0, pb1;
        if (kt + 1 < NT) {
            pa0 = *(const float4*)(Ap + (kt + 1) * 16);
            pa1 = *(const float4*)(Ap + (kt + 1) * 16 + 4);
            pb0 = *(const float4*)(Bp0 + (size_t)(kt + 1) * 16 * N);
            pb1 = *(const float4*)(Bp1 + (size_t)(kt + 1) * 16 * N);
        }
        uint32_t a[2][4], bf16[4][4];
        ldsm4(a[0], aad[buf][0]);
        ldsm4(a[1], aad[buf][1]);
#pragma unroll
        for (int jp = 0; jp < 4; jp++) ldsm4t(bf16[jp], bad[buf] + jp * 32);
#pragma unroll
        for (int i = 0; i < 2; i++)
#pragma unroll
            for (int j = 0; j < 8; j++)
                mma16816(acc[i][j], a[i], bf16[j >> 1][j & 1], bf16[j >> 1][2 + (j & 1)]);
        if (kt + 1 < NT) {
            buf ^= 1;
            fill_tiles(As[buf], Bs[buf], pa0, pa1, pb0, pb1, arow, ak, bkr, bcol);
            __syncthreads();
        }
    }

#pragma unroll
    for (int j = 0; j < 8; j++) {
        int c = col0 + wcol + j * 8 + tg * 2;
        float b0v = 0.f, b1v = 0.f;
        if (bias) { float2 bb = *(const float2*)(bias + c); b0v = bb.x; b1v = bb.y; }
#pragma unroll
        for (int i = 0; i < 2; i++) {
            int ra = row0 + wrow + i * 16 + gid;
            float v0 = acc[i][j][0] + b0v, v1 = acc[i][j][1] + b1v;
            float v2 = acc[i][j][2] + b0v, v3 = acc[i][j][3] + b1v;
            if (ACT == 2) {
                v0 = v0 >= 0.f ? v0 : SLOPE * v0; v1 = v1 >= 0.f ? v1 : SLOPE * v1;
                v2 = v2 >= 0.f ? v2 : SLOPE * v2; v3 = v3 >= 0.f ? v3 : SLOPE * v3;
            }
            *(float2*)((float*)C + (size_t)ra * N + c) = make_float2(v0, v1);
            *(float2*)((float*)C + (size_t)(ra + 8) * N + c) = make_float2(v2, v3);
        }
    }
}

// ---- fused conv: eb computed on-the-fly via mma; no eb buffer ----
// smem layout (bytes):
//   y_s   [64][260] f32 @ 0       (66560)
//   msg_s [128][264] f16 @ 66560  (67584)
//   ea_s  [128][24] f16 @ 134144  (6144)
//   We_s  [16][264] f16 @ 140288  (8448)
//   bm_s  [256] f32 @ 148736      (1024)
//   src_s [128] int @ 149760      (512)  -> total 150272
#define CV_SMEM 150272
__global__ void __launch_bounds__(256) conv_fused(
    const float* __restrict__ yzb,
    const float* __restrict__ ea0, const float* __restrict__ ea1,
    const float* __restrict__ We0, const float* __restrict__ We1,
    const float* __restrict__ bmp,
    const int* __restrict__ ptr0, const int* __restrict__ ptr1,
    const int2* __restrict__ pack0, const int2* __restrict__ pack1,
    const float* __restrict__ bs0, const float* __restrict__ bs1,
    float* __restrict__ xmb) {
    extern __shared__ char smem[];
    float* y_s = (float*)smem;
    __half* msg_s = (__half*)(smem + 66560);
    __half* ea_s = (__half*)(smem + 134144);
    __half* We_s = (__half*)(smem + 140288);
    float* bm_s = (float*)(smem + 148736);
    int* src_s = (int*)(smem + 149760);

    int g = blockIdx.x, t = threadIdx.x, z = blockIdx.y;
    const float* ea = z ? ea1 : ea0;
    const float* We = z ? We1 : We0;
    const int* ptr = z ? ptr1 : ptr0;
    const int2* pack = z ? pack1 : pack0;
    const float* bs = z ? bs1 : bs0;
    const float* yg = yzb + (size_t)z * 8388608 + (size_t)g * N_PG * 512;
    float* xo = xmb + (size_t)z * 4194304;

    // fill y (fp32), We (fp16), bm
    for (int i = t; i < N_PG * D_DIM; i += 256) {
        int n = i >> 8, d = i & 255;
        y_s[n * 260 + d] = yg[n * 512 + d];
    }
    for (int i = t; i < 16 * 256; i += 256) {
        int rr = i >> 8, cc = i & 255;
        We_s[rr * 264 + cc] = __float2half_rn(We[i]);
    }
    bm_s[t] = bmp[z * 256 + t];
    if (t < 128) src_s[t] = 0;
    __syncthreads();

    int w = t >> 5, lane = t & 31, gid = lane >> 2, tg = lane & 3;
    int i4 = t >> 6, dd = (t & 63) * 4;
    // mma addressing (constants per thread)
    uint32_t aaddr = su32(&ea_s[(w * 16 + (lane & 15)) * A_PAD + (lane >> 4) * 8]);
    int bk = (lane & 7) + ((lane >> 4) & 1) * 8;
    int bn8 = ((lane >> 3) & 1) * 8;

    for (int g4 = 0; g4 < 16; g4++) {
        int gn = g * N_PG + g4 * 4;
        int gs = ptr[gn], ge = ptr[gn + 4];
        int p0 = ptr[gn + i4], p1 = ptr[gn + i4 + 1];
        float ax = 0.f, ay = 0.f, az = 0.f, aw = 0.f;

        for (int R0 = gs; R0 < ge; R0 += 128) {
            int rc = ge - R0; if (rc > 128) rc = 128;
            // fill ea chunk + src
            {
                int el = t >> 1, hf = t & 1;
                if (el < rc) {
                    int2 pr = pack[R0 + el];
                    const float* er = ea + (size_t)pr.x * BOND_D + hf * 8;
                    float4 f0 = *(const float4*)er;
                    float4 f1 = *(const float4*)(er + 4);
                    __half2 h0 = __floats2half2_rn(f0.x, f0.y), h1 = __floats2half2_rn(f0.z, f0.w);
                    __half2 h2 = __floats2half2_rn(f1.x, f1.y), h3 = __floats2half2_rn(f1.z, f1.w);
                    uint4 u; u.x = *(uint32_t*)&h0; u.y = *(uint32_t*)&h1;
                    u.z = *(uint32_t*)&h2; u.w = *(uint32_t*)&h3;
                    *(uint4*)&ea_s[el * A_PAD + hf * 8] = u;
                    if (hf == 0) src_s[el] = pr.y;
                } else if (hf == 0) {
                    src_s[el] = 0;
                }
            }
            __syncthreads();
            // phase A: mma eb + y + bm -> relu -> msg (warp w owns edge rows 16w..16w+15)
            {
                uint32_t af[4];
                ldsm4(af, aaddr);
                int e0 = w * 16 + gid, e1 = e0 + 8;
                int s0 = src_s[e0] & 63, s1 = src_s[e1] & 63;
#pragma unroll
                for (int ng = 0; ng < 4; ng++) {
                    uint32_t bad = su32(&We_s[bk * 264 + ng * 64 + bn8]);
                    uint32_t bf[4][4];
#pragma unroll
                    for (int jp = 0; jp < 4; jp++) ldsm4t(bf[jp], bad + jp * 32);
                    float acc8[8][4];
#pragma unroll
                    for (int j = 0; j < 8; j++) {
                        acc8[j][0] = 0.f; acc8[j][1] = 0.f; acc8[j][2] = 0.f; acc8[j][3] = 0.f;
                        mma16816(acc8[j], af, bf[j >> 1][j & 1], bf[j >> 1][2 + (j & 1)]);
                    }
#pragma unroll
                    for (int j = 0; j < 8; j++) {
                        int c = ng * 64 + j * 8 + tg * 2;
                        float2 yv0 = *(float2*)&y_s[s0 * 260 + c];
                        float2 yv1 = *(float2*)&y_s[s1 * 260 + c];
                        float bmc0 = bm_s[c], bmc1 = bm_s[c + 1];
                        float v0 = fmaxf(acc8[j][0] + yv0.x + bmc0, 0.f);
                        float v1 = fmaxf(acc8[j][1] + yv0.y + bmc1, 0.f);
                        float v2 = fmaxf(acc8[j][2] + yv1.x + bmc0, 0.f);
                        float v3 = fmaxf(acc8[j][3] + yv1.y + bmc1, 0.f);
                        *(__half2*)&msg_s[e0 * 264 + c] = __floats2half2_rn(v0, v1);
                        *(__half2*)&msg_s[e1 * 264 + c] = __floats2half2_rn(v2, v3);
                    }
                }
            }
            __syncthreads();
            // phase B: node-centric register accumulation, CSR-ascending order
            {
                int lo = p0 > R0 ? p0 : R0;
                int hi = p1 < R0 + rc ? p1 : R0 + rc;
                for (int j2 = lo; j2 < hi; j2++) {
                    int el = j2 - R0;
                    uint2 m = *(uint2*)&msg_s[el * 264 + dd];
                    float2 m0 = __half22float2(*(__half2*)&m.x);
                    float2 m1 = __half22float2(*(__half2*)&m.y);
                    ax += m0.x; ay += m0.y; az += m1.x; aw += m1.y;
                }
            }
            __syncthreads();
        }
        // write out 4 nodes of this group
        {
            int n = g4 * 4 + i4;
            float4 zv = *(const float4*)(yg + (size_t)n * 512 + 256 + dd);
            float4 bsv = *(const float4*)(bs + dd);
            float4 r;
            r.x = fmaxf(zv.x + ax + bsv.x, 0.f);
            r.y = fmaxf(zv.y + ay + bsv.y, 0.f);
            r.z = fmaxf(zv.z + az + bsv.z, 0.f);
            r.w = fmaxf(zv.w + aw + bsv.w, 0.f);
            *(float4*)(xo + (size_t)(g * N_PG + n) * D_DIM + dd) = r;
        }
    }
}

// ---- dot_pool via mma (fp32 in, x1/16 on fill — exact; result x256) ----
__global__ void __launch_bounds__(256) dotpool_kernel(const float* __restrict__ xmb,
                                                      float* __restrict__ fus, int s) {
    extern __shared__ __half sm_h[];
    __half* a = sm_h;            // [64][264]
    __half* b = sm_h + 64 * 264;
    __shared__ float rm[256], rs[256];
    int g = blockIdx.x, t = threadIdx.x;
    int wid = t >> 5, lane = t & 31;
    const float* p1 = xmb + (size_t)g * N_PG * D_DIM;
    const float* p2 = xmb + 4194304 + (size_t)g * N_PG * D_DIM;
    for (int i = t; i < 2048; i += 256) {
        int n = i >> 5, c = (i & 31) * 8;
        float4 u0 = *(const float4*)(p1 + (size_t)n * 256 + c);
        float4 u1 = *(const float4*)(p1 + (size_t)n * 256 + c + 4);
        __half2 h0 = __floats2half2_rn(u0.x * 0.0625f, u0.y * 0.0625f);
        __half2 h1 = __floats2half2_rn(u0.z * 0.0625f, u0.w * 0.0625f);
        __half2 h2 = __floats2half2_rn(u1.x * 0.0625f, u1.y * 0.0625f);
        __half2 h3 = __floats2half2_rn(u1.z * 0.0625f, u1.w * 0.0625f);
        uint4 uu; uu.x = *(uint32_t*)&h0; uu.y = *(uint32_t*)&h1; uu.z = *(uint32_t*)&h2; uu.w = *(uint32_t*)&h3;
        *(uint4*)&a[n * 264 + c] = uu;
        u0 = *(const float4*)(p2 + (size_t)n * 256 + c);
        u1 = *(const float4*)(p2 + (size_t)n * 256 + c + 4);
        h0 = __floats2half2_rn(u0.x * 0.0625f, u0.y * 0.0625f);
        h1 = __floats2half2_rn(u0.z * 0.0625f, u0.w * 0.0625f);
        h2 = __floats2half2_rn(u1.x * 0.0625f, u1.y * 0.0625f);
        h3 = __floats2half2_rn(u1.z * 0.0625f, u1.w * 0.0625f);
        uu.x = *(uint32_t*)&h0; uu.y = *(uint32_t*)&h1; uu.z = *(uint32_t*)&h2; uu.w = *(uint32_t*)&h3;
        *(uint4*)&b[n * 264 + c] = uu;
    }
    __syncthreads();
    int rt = (wid & 3) * 16, cb = (wid >> 2) * 32;
    uint32_t aaddr = su32(&a[(rt + (lane & 15)) * 264 + (lane >> 4) * 8]);
    uint32_t baddr0 = su32(&b[(cb + (lane & 7) + ((lane >> 4) & 1) * 8) * 264 + ((lane >> 3) & 1) * 8]);
    uint32_t baddr1 = baddr0 + 16 * 264 * 2;
    float acc[4][4];
#pragma unroll
    for (int i = 0; i < 4; i++)
#pragma unroll
        for (int j = 0; j < 4; j++) acc[i][j] = 0.f;
#pragma unroll
    for (int kk = 0; kk < 16; kk++) {
        uint32_t af[4], b0[4], b1[4];
        ldsm4(af, aaddr + kk * 32);
        ldsm4(b0, baddr0 + kk * 32);
        ldsm4(b1, baddr1 + kk * 32);
        mma16816(acc[0], af, b0[0], b0[1]);
        mma16816(acc[1], af, b0[2], b0[3]);
        mma16816(acc[2], af, b1[0], b1[1]);
        mma16816(acc[3], af, b1[2], b1[3]);
    }
    float lmax = -3.4e38f, ls = 0.f;
#pragma unroll
    for (int i = 0; i < 4; i++)
#pragma unroll
        for (int j = 0; j < 4; j++) { lmax = fmaxf(lmax, acc[i][j]); ls += acc[i][j]; }
    rm[t] = lmax; rs[t] = ls;
    __syncthreads();
    for (int o = 128; o > 0; o >>= 1) {
        if (t < o) { rm[t] = fmaxf(rm[t], rm[t + o]); rs[t] += rs[t + o]; }
        __syncthreads();
    }
    if (t == 0) {
        fus[g * 6 + 2 * s] = 256.f * rm[0];
        fus[g * 6 + 2 * s + 1] = 256.f * rs[0] / 4096.f;
    }
}

// ---- readout, merged via blockIdx.y ----
__global__ void readout_kernel(const float* __restrict__ xmb, float* __restrict__ rb) {
    __shared__ int ord[3];
    int g = blockIdx.x, t = threadIdx.x, z = blockIdx.y;
    const float* xg = xmb + (size_t)z * 4194304 + (size_t)g * N_PG * D_DIM;
    float* r = rb + (size_t)z * 327680;
    float s = 0.f;
    for (int n = 0; n < N_PG; n++) s += xg[n * D_DIM + t];
    r[g * 1280 + t] = s / 64.f;
    r[g * 1280 + 256 + t] = s / 64.f;   // sum as mean; Wf rows x64
    if (t < 32) {
        float v0 = xg[t * D_DIM + 255], v1 = xg[(t + 32) * D_DIM + 255];
        int i0 = t, i1 = t + 32;
        for (int k = 0; k < 3; k++) {
            float cv; int bi;
            if (v0 > v1 || (v0 == v1 && i0 < i1)) { cv = v0; bi = i0; } else { cv = v1; bi = i1; }
            for (int o = 16; o > 0; o >>= 1) {
                float ov = __shfl_down_sync(0xffffffffu, cv, o);
                int oi = __shfl_down_sync(0xffffffffu, bi, o);
                if (ov > cv || (ov == cv && oi < bi)) { cv = ov; bi = oi; }
            }
            bi = __shfl_sync(0xffffffffu, bi, 0);
            if (t == 0) ord[k] = bi;
            if (bi == i0) v0 = -3.4e38f;
            if (bi == i1) v1 = -3.4e38f;
        }
    }
    __syncthreads();
    for (int k = 0; k < 3; k++) r[g * 1280 + 512 + k * 256 + t] = xg[ord[k] * D_DIM + t];
}

// ---- head ----
__global__ void head_kernel(const float* __restrict__ ob,
                            const float* __restrict__ fus, const float* __restrict__ Wo1,
                            const float* __restrict__ bo1, const float* __restrict__ Wo2,
                            const float* __restrict__ bo2, float* __restrict__ out) {
    __shared__ float cat[518];
    __shared__ float r0[256], r1a[256];
    int g = blockIdx.x, t = threadIdx.x;
    cat[t] = ob[g * 256 + t];
    cat[256 + t] = ob[65536 + g * 256 + t];
    if (t < 6) cat[512 + t] = fus[g * 6 + t];
    __syncthreads();
    float h = bo1[t];
    for (int k = 0; k < 518; k++) h += cat[k] * Wo1[k * 256 + t];
    r0[t] = h * Wo2[t * 2];
    r1a[t] = h * Wo2[t * 2 + 1];
    __syncthreads();
    for (int o = 128; o > 0; o >>= 1) {
        if (t < o) { r0[t] += r0[t + o]; r1a[t] += r1a[t + o]; }
        __syncthreads();
    }
    if (t == 0) { out[g * 2] = r0[0] + bo2[0]; out[g * 2 + 1] = r1a[0] + bo2[1]; }
}

extern "C" void kernel_launch(void* const* d_in, const int* in_sizes, int n_in,
                              void* d_out, int out_size) {
    const float* x1 = (const float*)d_in[0];
    const void* ei1 = d_in[1];
    const float* ea1 = (const float*)d_in[2];
    const float* x2 = (const float*)d_in[4];
    const void* ei2 = d_in[5];
    const float* ea2 = (const float*)d_in[6];
    const float* W0_1 = (const float*)d_in[8];  const float* b0_1 = (const float*)d_in[9];
    const float* W0_2 = (const float*)d_in[10]; const float* b0_2 = (const float*)d_in[11];
    const float* Wn1 = (const float*)d_in[12];  const float* We1 = (const float*)d_in[13];
    const float* bm1 = (const float*)d_in[14];  const float* Ws1 = (const float*)d_in[15];
    const float* bs1 = (const float*)d_in[16];
    const float* Wn2 = (const float*)d_in[17];  const float* We2 = (const float*)d_in[18];
    const float* bm2 = (const float*)d_in[19];  const float* Ws2 = (const float*)d_in[20];
    const float* bs2 = (const float*)d_in[21];
    const float* Wf1 = (const float*)d_in[22];  const float* bf1 = (const float*)d_in[23];
    const float* Wf2 = (const float*)d_in[24];  const float* bf2 = (const float*)d_in[25];
    const float* Wo1 = (const float*)d_in[26];  const float* bo1 = (const float*)d_in[27];
    const float* Wo2 = (const float*)d_in[28];  const float* bo2 = (const float*)d_in[29];
    float* out = (float*)d_out;

    void* p;
    cudaGetSymbolAddress(&p, g_yz);   float* yz = (float*)p;
    cudaGetSymbolAddress(&p, g_xm);   float* xm = (float*)p;
    cudaGetSymbolAddress(&p, g_wcat); float* wc = (float*)p;
    cudaGetSymbolAddress(&p, g_wf);   float* wf = (float*)p;
    cudaGetSymbolAddress(&p, g_r);    float* r = (float*)p;
    cudaGetSymbolAddress(&p, g_o);    float* o = (float*)p;
    cudaGetSymbolAddress(&p, g_b0p);  float* b0p = (float*)p;
    cudaGetSymbolAddress(&p, g_bmp);  float* bmp = (float*)p;
    cudaGetSymbolAddress(&p, g_bfp);  float* bfp = (float*)p;
    cudaGetSymbolAddress(&p, g_fus);  float* fus = (float*)p;
    cudaGetSymbolAddress(&p, g_ptr1); int* ptr1 = (int*)p;
    cudaGetSymbolAddress(&p, g_ptr2); int* ptr2 = (int*)p;
    cudaGetSymbolAddress(&p, g_pack1); int2* pack1 = (int2*)p;
    cudaGetSymbolAddress(&p, g_pack2); int2* pack2 = (int2*)p;

    cudaFuncSetAttribute(conv_fused, cudaFuncAttributeMaxDynamicSharedMemorySize, CV_SMEM);
    cudaFuncSetAttribute(dotpool_kernel, cudaFuncAttributeMaxDynamicSharedMemorySize, 2 * 64 * 264 * 2);

    // setup
    detect_kernel<<<1, 512>>>((const unsigned*)ei1, (const unsigned*)ei2);
    build_csr<<<dim3(B_GR, 2), 256>>>(ei1, ei2, ptr1, ptr2, pack1, pack2);
    pack_all<<<1536, 256>>>(Wn1, Ws1, Wn2, Ws2, Wf1, Wf2, b0_1, b0_2, bm1, bm2, bf1, bf2,
                            wc, wf, b0p, bmp, bfp);

    // input layer both mols
    dim3 gT(2, T_TOT / 128, 2);
    hgemm<2, float><<<gT, 256>>>(x1, x2, W0_1, W0_2, b0p, b0p + 256, xm, xm + 4194304,
                                 T_TOT, 256, 128);

    // loop: yz gemm -> fused conv -> dotpool
    dim3 gYZ(4, T_TOT / 128, 2);   // N=512, both mols
    for (int s = 0; s < 3; s++) {
        hgemm<0, float><<<gYZ, 256>>>(xm, xm + 4194304, wc, wc + 131072, nullptr, nullptr,
                                      yz, yz + 8388608, T_TOT, 512, 256);
        conv_fused<<<dim3(B_GR, 2), 256, CV_SMEM>>>(yz, ea1, ea2, We1, We2, bmp,
                                                    ptr1, ptr2, pack1, pack2, bs1, bs2, xm);
        dotpool_kernel<<<B_GR, 256, 2 * 64 * 264 * 2>>>(xm, fus, s);
    }

    // readout / Wf / head
    readout_kernel<<<dim3(B_GR, 2), 256>>>(xm, r);
    dim3 gF(2, 2, 2);
    hgemm<0, float><<<gF, 256>>>(r, r + 327680, wf, wf + 327680, bfp, bfp + 256,
                                 o, o + 65536, 256, 256, 1280);
    head_kernel<<<B_GR, 256>>>(o, fus, Wo1, bo1, Wo2, bo2, out);
}

// round 17
// speedup vs baseline: 1.6205x; 1.0785x over previous
#include <cuda_runtime.h>
#include <cuda_fp16.h>
#include <cstdint>
#include <cstddef>

#define B_GR 256
#define N_PG 64
#define D_DIM 256
#define T_TOT 16384
#define E_TOT 524288
#define E_PG 2048
#define BOND_D 16
#define SLOPE 0.22916666666666666f

// planes: index 0 = mol1, 1 = mol2
__device__ __half g_yz[2ull * 8388608];        // [2][T][512] fp16: y | z
__device__ float g_xm[2ull * 4194304];         // [2][T][256]
__device__ float g_wcat[2 * 131072];           // [2][256][512] = Wn | Ws
__device__ float g_wf[2 * 327680];             // [2] Wf, rows 256-511 x64
__device__ float g_r[2 * 327680];              // [2][B][1280]
__device__ float g_o[2 * 65536];               // [2][B][256]
__device__ float g_b0p[2 * 256];
__device__ float g_bmp[2 * 256];
__device__ float g_bfp[2 * 256];
__device__ float g_fus[B_GR * 6];
__device__ int g_ptr1[T_TOT + 1];
__device__ int g_ptr2[T_TOT + 1];
__device__ int2 g_pack1[E_TOT];                // (global edge id, src_local)
__device__ int2 g_pack2[E_TOT];

// ---- 1: merged setup: per-graph CSR (blocks 0-511, local dtype detect) + packs ----
__global__ void setup_kernel(const void* __restrict__ ei0, const void* __restrict__ ei1,
                             int* __restrict__ ptr0, int* __restrict__ ptr1,
                             int2* __restrict__ pack0, int2* __restrict__ pack1,
                             const float* Wn1, const float* Ws1, const float* Wn2, const float* Ws2,
                             const float* Wf1, const float* Wf2,
                             const float* b0_1, const float* b0_2,
                             const float* bm1, const float* bm2,
                             const float* bf1, const float* bf2,
                             float* wcat, float* wf, float* b0p, float* bmp, float* bfp) {
    int b = blockIdx.x, t = threadIdx.x;
    if (b < 512) {
        __shared__ int sl[E_PG], dl[E_PG], cnt[N_PG], base[N_PG];
        __shared__ int flag;
        int which = b >> 8, g = b & 255;
        const void* eidx = which ? ei1 : ei0;
        int* ptr = which ? ptr1 : ptr0;
        int2* pack = which ? pack1 : pack0;
        // local dtype detect: odd 32-bit words of 256 entries of this graph's src row.
        // int64 LE nonneg<2^31 => all zero; int32 data => random node ids (P(all 0)=64^-256).
        if (t == 0) flag = 0;
        __syncthreads();
        {
            const unsigned* ew = (const unsigned*)eidx;
            if (ew[2 * ((long long)g * E_PG + t) + 1]) flag = 1;   // benign race
        }
        __syncthreads();
        int is64 = !flag;
        if (t < N_PG) cnt[t] = 0;
        __syncthreads();
        for (int e = t; e < E_PG; e += 256) {
            long long ge = (long long)g * E_PG + e;
            int s, d;
            if (is64) {
                s = (int)((const long long*)eidx)[ge];
                d = (int)((const long long*)eidx)[(long long)E_TOT + ge];
            } else {
                s = ((const int*)eidx)[ge];
                d = ((const int*)eidx)[(long long)E_TOT + ge];
            }
            sl[e] = s - g * N_PG;
            dl[e] = d - g * N_PG;
            atomicAdd(&cnt[dl[e]], 1);
        }
        __syncthreads();
        if (t == 0) {
            int run = 0;
            for (int n = 0; n < N_PG; n++) {
                base[n] = run;
                ptr[g * N_PG + n] = g * E_PG + run;
                run += cnt[n];
            }
            if (g == 0) ptr[T_TOT] = E_TOT;
        }
        __syncthreads();
        if (t < N_PG) {
            int p = g * E_PG + base[t];
            for (int e = 0; e < E_PG; e++)
                if (dl[e] == t) { pack[p] = make_int2(g * E_PG + e, sl[e]); p++; }
        }
    } else {
        int k = b - 512;  // 0..1535
        if (k < 256) {
            wcat[k * 512 + t] = Wn1[k * 256 + t];
            wcat[k * 512 + 256 + t] = Ws1[k * 256 + t];
            wcat[131072 + k * 512 + t] = Wn2[k * 256 + t];
            wcat[131072 + k * 512 + 256 + t] = Ws2[k * 256 + t];
            if (k == 0) { b0p[t] = b0_1[t]; bmp[t] = bm1[t]; bfp[t] = bf1[t]; }
            if (k == 1) { b0p[256 + t] = b0_2[t]; bmp[256 + t] = bm2[t]; bfp[256 + t] = bf2[t]; }
        } else {
            int kk = k - 256;
            float sc = (kk >= 256 && kk < 512) ? 64.f : 1.f;
            wf[kk * 256 + t] = Wf1[kk * 256 + t] * sc;
            wf[327680 + kk * 256 + t] = Wf2[kk * 256 + t] * sc;
        }
    }
}

// ---- ptx helpers ----
__device__ __forceinline__ uint32_t su32(const void* p) {
    return (uint32_t)__cvta_generic_to_shared(p);
}
__device__ __forceinline__ void ldsm4(uint32_t* r, uint32_t addr) {
    asm volatile("ldmatrix.sync.aligned.m8n8.x4.shared.b16 {%0,%1,%2,%3}, [%4];"
                 : "=r"(r[0]), "=r"(r[1]), "=r"(r[2]), "=r"(r[3]) : "r"(addr));
}
__device__ __forceinline__ void ldsm4t(uint32_t* r, uint32_t addr) {
    asm volatile("ldmatrix.sync.aligned.m8n8.x4.trans.shared.b16 {%0,%1,%2,%3}, [%4];"
                 : "=r"(r[0]), "=r"(r[1]), "=r"(r[2]), "=r"(r[3]) : "r"(addr));
}
__device__ __forceinline__ void mma16816(float* c, const uint32_t* a, uint32_t b0, uint32_t b1) {
    asm volatile(
        "mma.sync.aligned.m16n8k16.row.col.f32.f16.f16.f32 "
        "{%0,%1,%2,%3},{%4,%5,%6,%7},{%8,%9},{%0,%1,%2,%3};"
        : "+f"(c[0]), "+f"(c[1]), "+f"(c[2]), "+f"(c[3])
        : "r"(a[0]), "r"(a[1]), "r"(a[2]), "r"(a[3]), "r"(b0), "r"(b1));
}

#define A_PAD 24
#define B_PAD 136

__device__ __forceinline__ void fill_tiles(__half* as_, __half* bs_,
                                           float4 a0, float4 a1, float4 b0, float4 b1,
                                           int arow, int ak, int bkr, int bcol) {
    __half2 h0 = __floats2half2_rn(a0.x, a0.y), h1 = __floats2half2_rn(a0.z, a0.w);
    __half2 h2 = __floats2half2_rn(a1.x, a1.y), h3 = __floats2half2_rn(a1.z, a1.w);
    uint4 u;
    u.x = *(uint32_t*)&h0; u.y = *(uint32_t*)&h1; u.z = *(uint32_t*)&h2; u.w = *(uint32_t*)&h3;
    *(uint4*)&as_[arow * A_PAD + ak] = u;
    __half2 p0 = __floats2half2_rn(b0.x, b0.y), p1 = __floats2half2_rn(b0.z, b0.w);
    uint2 v; v.x = *(uint32_t*)&p0; v.y = *(uint32_t*)&p1;
    *(uint2*)&bs_[bkr * B_PAD + bcol] = v;
    p0 = __floats2half2_rn(b1.x, b1.y); p1 = __floats2half2_rn(b1.z, b1.w);
    v.x = *(uint32_t*)&p0; v.y = *(uint32_t*)&p1;
    *(uint2*)&bs_[(bkr + 8) * B_PAD + bcol] = v;
}

// ---- fp32-in fp16-mma GEMM, molecule-merged via blockIdx.z ----
// OutT==__half: SMEM-staged coalesced epilogue.
template <int ACT, typename OutT>
__global__ void __launch_bounds__(256) hgemm(const float* __restrict__ A0, const float* __restrict__ A1,
                                             const float* __restrict__ B0, const float* __restrict__ B1,
                                             const float* __restrict__ bias0, const float* __restrict__ bias1,
                                             OutT* __restrict__ C0, OutT* __restrict__ C1,
                                             int M, int N, int K) {
    __shared__ __align__(16) __half As[2][128 * A_PAD];
    __shared__ __align__(16) __half Bs[2][16 * B_PAD];
    int z = blockIdx.z;
    const float* A = z ? A1 : A0;
    const float* Bm = z ? B1 : B0;
    const float* bias = z ? bias1 : bias0;
    OutT* C = z ? C1 : C0;
    int tid = threadIdx.x;
    int wid = tid >> 5, lane = tid & 31;
    int gid = lane >> 2, tg = lane & 3;
    int row0 = blockIdx.y * 128, col0 = blockIdx.x * 128;
    int wrow = (wid & 3) * 32, wcol = (wid >> 2) * 64;
    int arow = tid >> 1, ak = (tid & 1) * 8;
    int bkr = tid >> 5, bcol = (tid & 31) * 4;
    const float* Ap = A + (size_t)(row0 + arow) * K + ak;
    const float* Bp0 = Bm + (size_t)bkr * N + col0 + bcol;
    const float* Bp1 = Bm + (size_t)(bkr + 8) * N + col0 + bcol;

    uint32_t aad[2][2], bad[2];
    {
        int arw = (lane & 15), acl = (lane >> 4) * 8;
        int bk = (lane & 7) + ((lane >> 4) & 1) * 8;
        int bn = wcol + ((lane >> 3) & 1) * 8;
#pragma unroll
        for (int b = 0; b < 2; b++) {
            aad[b][0] = su32(&As[b][(wrow + arw) * A_PAD + acl]);
            aad[b][1] = su32(&As[b][(wrow + 16 + arw) * A_PAD + acl]);
            bad[b] = su32(&Bs[b][bk * B_PAD + bn]);
        }
    }

    float acc[2][8][4];
#pragma unroll
    for (int i = 0; i < 2; i++)
#pragma unroll
        for (int j = 0; j < 8; j++)
#pragma unroll
            for (int q = 0; q < 4; q++) acc[i][j][q] = 0.f;

    {
        float4 a0 = *(const float4*)Ap;
        float4 a1 = *(const float4*)(Ap + 4);
        float4 b0 = *(const float4*)Bp0;
        float4 b1 = *(const float4*)Bp1;
        fill_tiles(As[0], Bs[0], a0, a1, b0, b1, arow, ak, bkr, bcol);
    }
    __syncthreads();

    int NT = K >> 4;
    int buf = 0;
    for (int kt = 0; kt < NT; kt++) {
        float4 pa0, pa1, pb0, pb1;
        if (kt + 1 < NT) {
            pa0 = *(const float4*)(Ap + (kt + 1) * 16);
            pa1 = *(const float4*)(Ap + (kt + 1) * 16 + 4);
            pb0 = *(const float4*)(Bp0 + (size_t)(kt + 1) * 16 * N);
            pb1 = *(const float4*)(Bp1 + (size_t)(kt + 1) * 16 * N);
        }
        uint32_t a[2][4], bf16[4][4];
        ldsm4(a[0], aad[buf][0]);
        ldsm4(a[1], aad[buf][1]);
#pragma unroll
        for (int jp = 0; jp < 4; jp++) ldsm4t(bf16[jp], bad[buf] + jp * 32);
#pragma unroll
        for (int i = 0; i < 2; i++)
#pragma unroll
            for (int j = 0; j < 8; j++)
                mma16816(acc[i][j], a[i], bf16[j >> 1][j & 1], bf16[j >> 1][2 + (j & 1)]);
        if (kt + 1 < NT) {
            buf ^= 1;
            fill_tiles(As[buf], Bs[buf], pa0, pa1, pb0, pb1, arow, ak, bkr, bcol);
            __syncthreads();
        }
    }

    if constexpr (sizeof(OutT) == 2) {
        __shared__ __align__(16) __half St[64 * 136];
        __syncthreads();
#pragma unroll
        for (int ch = 0; ch < 2; ch++) {
            if (((wid & 3) >> 1) == ch) {
                int wrl = ((wid & 3) & 1) * 32;
#pragma unroll
                for (int j = 0; j < 8; j++) {
                    int cc = wcol + j * 8 + tg * 2;
                    float b0v = 0.f, b1v = 0.f;
                    if (bias) { float2 bb = *(const float2*)(bias + col0 + cc); b0v = bb.x; b1v = bb.y; }
#pragma unroll
                    for (int i = 0; i < 2; i++) {
                        int lr = wrl + i * 16 + gid;
                        float v0 = acc[i][j][0] + b0v, v1 = acc[i][j][1] + b1v;
                        float v2 = acc[i][j][2] + b0v, v3 = acc[i][j][3] + b1v;
                        if (ACT == 2) {
                            v0 = v0 >= 0.f ? v0 : SLOPE * v0; v1 = v1 >= 0.f ? v1 : SLOPE * v1;
                            v2 = v2 >= 0.f ? v2 : SLOPE * v2; v3 = v3 >= 0.f ? v3 : SLOPE * v3;
                        }
                        *(__half2*)&St[lr * 136 + cc] = __floats2half2_rn(v0, v1);
                        *(__half2*)&St[(lr + 8) * 136 + cc] = __floats2half2_rn(v2, v3);
                    }
                }
            }
            __syncthreads();
#pragma unroll
            for (int u = 0; u < 4; u++) {
                int q = tid + 256 * u;
                int lr = q >> 4, cc = (q & 15) * 8;
                uint4 val = *(uint4*)&St[lr * 136 + cc];
                *(uint4*)((__half*)C + (size_t)(row0 + ch * 64 + lr) * N + col0 + cc) = val;
            }
            __syncthreads();
        }
    } else {
#pragma unroll
        for (int j = 0; j < 8; j++) {
            int c = col0 + wcol + j * 8 + tg * 2;
            float b0v = 0.f, b1v = 0.f;
            if (bias) { float2 bb = *(const float2*)(bias + c); b0v = bb.x; b1v = bb.y; }
#pragma unroll
            for (int i = 0; i < 2; i++) {
                int ra = row0 + wrow + i * 16 + gid;
                float v0 = acc[i][j][0] + b0v, v1 = acc[i][j][1] + b1v;
                float v2 = acc[i][j][2] + b0v, v3 = acc[i][j][3] + b1v;
                if (ACT == 2) {
                    v0 = v0 >= 0.f ? v0 : SLOPE * v0; v1 = v1 >= 0.f ? v1 : SLOPE * v1;
                    v2 = v2 >= 0.f ? v2 : SLOPE * v2; v3 = v3 >= 0.f ? v3 : SLOPE * v3;
                }
                *(float2*)((float*)C + (size_t)ra * N + c) = make_float2(v0, v1);
                *(float2*)((float*)C + (size_t)(ra + 8) * N + c) = make_float2(v2, v3);
            }
        }
    }
}

// ---- fused conv: eb computed on-the-fly via mma; fp16 yz inputs ----
// smem (bytes): y_s [64][264] f16 @0 (33792); msg_s [128][264] f16 @33792 (67584);
//   ea_s [128][24] f16 @101376 (6144); We_s [16][264] f16 @107520 (8448);
//   bm_s [256] f32 @115968 (1024); src_s [128] int @116992 (512) -> 117504
#define CV_SMEM 117504
__global__ void __launch_bounds__(256) conv_fused(
    const __half* __restrict__ yzb,
    const float* __restrict__ ea0, const float* __restrict__ ea1,
    const float* __restrict__ We0, const float* __restrict__ We1,
    const float* __restrict__ bmp,
    const int* __restrict__ ptr0, const int* __restrict__ ptr1,
    const int2* __restrict__ pack0, const int2* __restrict__ pack1,
    const float* __restrict__ bs0, const float* __restrict__ bs1,
    float* __restrict__ xmb) {
    extern __shared__ char smem[];
    __half* y_s = (__half*)smem;
    __half* msg_s = (__half*)(smem + 33792);
    __half* ea_s = (__half*)(smem + 101376);
    __half* We_s = (__half*)(smem + 107520);
    float* bm_s = (float*)(smem + 115968);
    int* src_s = (int*)(smem + 116992);

    int g = blockIdx.x, t = threadIdx.x, z = blockIdx.y;
    const float* ea = z ? ea1 : ea0;
    const float* We = z ? We1 : We0;
    const int* ptr = z ? ptr1 : ptr0;
    const int2* pack = z ? pack1 : pack0;
    const float* bs = z ? bs1 : bs0;
    const __half* yg = yzb + (size_t)z * 8388608 + (size_t)g * N_PG * 512;
    float* xo = xmb + (size_t)z * 4194304;

    // fill y (fp16 direct), We (fp16), bm
    for (int i = t; i < N_PG * 32; i += 256) {
        int n = i >> 5, c = (i & 31) * 8;
        *(uint4*)&y_s[n * 264 + c] = *(const uint4*)(yg + (size_t)n * 512 + c);
    }
    for (int i = t; i < 16 * 256; i += 256) {
        int rr = i >> 8, cc = i & 255;
        We_s[rr * 264 + cc] = __float2half_rn(We[i]);
    }
    bm_s[t] = bmp[z * 256 + t];
    if (t < 128) src_s[t] = 0;
    __syncthreads();

    int w = t >> 5, lane = t & 31, gid = lane >> 2, tg = lane & 3;
    int i4 = t >> 6, dd = (t & 63) * 4;
    uint32_t aaddr = su32(&ea_s[(w * 16 + (lane & 15)) * A_PAD + (lane >> 4) * 8]);
    int bk = (lane & 7) + ((lane >> 4) & 1) * 8;
    int bn8 = ((lane >> 3) & 1) * 8;

    for (int g4 = 0; g4 < 16; g4++) {
        int gn = g * N_PG + g4 * 4;
        int gs = ptr[gn], ge = ptr[gn + 4];
        int p0 = ptr[gn + i4], p1 = ptr[gn + i4 + 1];
        float ax = 0.f, ay = 0.f, az = 0.f, aw = 0.f;

        for (int R0 = gs; R0 < ge; R0 += 128) {
            int rc = ge - R0; if (rc > 128) rc = 128;
            {
                int el = t >> 1, hf = t & 1;
                if (el < rc) {
                    int2 pr = pack[R0 + el];
                    const float* er = ea + (size_t)pr.x * BOND_D + hf * 8;
                    float4 f0 = *(const float4*)er;
                    float4 f1 = *(const float4*)(er + 4);
                    __half2 h0 = __floats2half2_rn(f0.x, f0.y), h1 = __floats2half2_rn(f0.z, f0.w);
                    __half2 h2 = __floats2half2_rn(f1.x, f1.y), h3 = __floats2half2_rn(f1.z, f1.w);
                    uint4 u; u.x = *(uint32_t*)&h0; u.y = *(uint32_t*)&h1;
                    u.z = *(uint32_t*)&h2; u.w = *(uint32_t*)&h3;
                    *(uint4*)&ea_s[el * A_PAD + hf * 8] = u;
                    if (hf == 0) src_s[el] = pr.y;
                } else if (hf == 0) {
                    src_s[el] = 0;
                }
            }
            __syncthreads();
            {
                uint32_t af[4];
                ldsm4(af, aaddr);
                int e0 = w * 16 + gid, e1 = e0 + 8;
                int s0 = src_s[e0] & 63, s1 = src_s[e1] & 63;
#pragma unroll
                for (int ng = 0; ng < 4; ng++) {
                    uint32_t bad = su32(&We_s[bk * 264 + ng * 64 + bn8]);
                    uint32_t bf[4][4];
#pragma unroll
                    for (int jp = 0; jp < 4; jp++) ldsm4t(bf[jp], bad + jp * 32);
                    float acc8[8][4];
#pragma unroll
                    for (int j = 0; j < 8; j++) {
                        acc8[j][0] = 0.f; acc8[j][1] = 0.f; acc8[j][2] = 0.f; acc8[j][3] = 0.f;
                        mma16816(acc8[j], af, bf[j >> 1][j & 1], bf[j >> 1][2 + (j & 1)]);
                    }
#pragma unroll
                    for (int j = 0; j < 8; j++) {
                        int c = ng * 64 + j * 8 + tg * 2;
                        float2 yv0 = __half22float2(*(__half2*)&y_s[s0 * 264 + c]);
                        float2 yv1 = __half22float2(*(__half2*)&y_s[s1 * 264 + c]);
                        float bmc0 = bm_s[c], bmc1 = bm_s[c + 1];
                        float v0 = fmaxf(acc8[j][0] + yv0.x + bmc0, 0.f);
                        float v1 = fmaxf(acc8[j][1] + yv0.y + bmc1, 0.f);
                        float v2 = fmaxf(acc8[j][2] + yv1.x + bmc0, 0.f);
                        float v3 = fmaxf(acc8[j][3] + yv1.y + bmc1, 0.f);
                        *(__half2*)&msg_s[e0 * 264 + c] = __floats2half2_rn(v0, v1);
                        *(__half2*)&msg_s[e1 * 264 + c] = __floats2half2_rn(v2, v3);
                    }
                }
            }
            __syncthreads();
            {
                int lo = p0 > R0 ? p0 : R0;
                int hi = p1 < R0 + rc ? p1 : R0 + rc;
                for (int j2 = lo; j2 < hi; j2++) {
                    int el = j2 - R0;
                    uint2 m = *(uint2*)&msg_s[el * 264 + dd];
                    float2 m0 = __half22float2(*(__half2*)&m.x);
                    float2 m1 = __half22float2(*(__half2*)&m.y);
                    ax += m0.x; ay += m0.y; az += m1.x; aw += m1.y;
                }
            }
            __syncthreads();
        }
        {
            int n = g4 * 4 + i4;
            uint2 zr = *(const uint2*)(yg + (size_t)n * 512 + 256 + dd);
            float2 z0 = __half22float2(*(__half2*)&zr.x), z1 = __half22float2(*(__half2*)&zr.y);
            float4 bsv = *(const float4*)(bs + dd);
            float4 r;
            r.x = fmaxf(z0.x + ax + bsv.x, 0.f);
            r.y = fmaxf(z0.y + ay + bsv.y, 0.f);
            r.z = fmaxf(z1.x + az + bsv.z, 0.f);
            r.w = fmaxf(z1.y + aw + bsv.w, 0.f);
            *(float4*)(xo + (size_t)(g * N_PG + n) * D_DIM + dd) = r;
        }
    }
}

// ---- dot_pool via mma (fp32 in, x1/16 on fill — exact; result x256) ----
__global__ void __launch_bounds__(256) dotpool_kernel(const float* __restrict__ xmb,
                                                      float* __restrict__ fus, int s) {
    extern __shared__ __half sm_h[];
    __half* a = sm_h;            // [64][264]
    __half* b = sm_h + 64 * 264;
    __shared__ float rm[256], rs[256];
    int g = blockIdx.x, t = threadIdx.x;
    int wid = t >> 5, lane = t & 31;
    const float* p1 = xmb + (size_t)g * N_PG * D_DIM;
    const float* p2 = xmb + 4194304 + (size_t)g * N_PG * D_DIM;
    for (int i = t; i < 2048; i += 256) {
        int n = i >> 5, c = (i & 31) * 8;
        float4 u0 = *(const float4*)(p1 + (size_t)n * 256 + c);
        float4 u1 = *(const float4*)(p1 + (size_t)n * 256 + c + 4);
        __half2 h0 = __floats2half2_rn(u0.x * 0.0625f, u0.y * 0.0625f);
        __half2 h1 = __floats2half2_rn(u0.z * 0.0625f, u0.w * 0.0625f);
        __half2 h2 = __floats2half2_rn(u1.x * 0.0625f, u1.y * 0.0625f);
        __half2 h3 = __floats2half2_rn(u1.z * 0.0625f, u1.w * 0.0625f);
        uint4 uu; uu.x = *(uint32_t*)&h0; uu.y = *(uint32_t*)&h1; uu.z = *(uint32_t*)&h2; uu.w = *(uint32_t*)&h3;
        *(uint4*)&a[n * 264 + c] = uu;
        u0 = *(const float4*)(p2 + (size_t)n * 256 + c);
        u1 = *(const float4*)(p2 + (size_t)n * 256 + c + 4);
        h0 = __floats2half2_rn(u0.x * 0.0625f, u0.y * 0.0625f);
        h1 = __floats2half2_rn(u0.z * 0.0625f, u0.w * 0.0625f);
        h2 = __floats2half2_rn(u1.x * 0.0625f, u1.y * 0.0625f);
        h3 = __floats2half2_rn(u1.z * 0.0625f, u1.w * 0.0625f);
        uu.x = *(uint32_t*)&h0; uu.y = *(uint32_t*)&h1; uu.z = *(uint32_t*)&h2; uu.w = *(uint32_t*)&h3;
        *(uint4*)&b[n * 264 + c] = uu;
    }
    __syncthreads();
    int rt = (wid & 3) * 16, cb = (wid >> 2) * 32;
    uint32_t aaddr = su32(&a[(rt + (lane & 15)) * 264 + (lane >> 4) * 8]);
    uint32_t baddr0 = su32(&b[(cb + (lane & 7) + ((lane >> 4) & 1) * 8) * 264 + ((lane >> 3) & 1) * 8]);
    uint32_t baddr1 = baddr0 + 16 * 264 * 2;
    float acc[4][4];
#pragma unroll
    for (int i = 0; i < 4; i++)
#pragma unroll
        for (int j = 0; j < 4; j++) acc[i][j] = 0.f;
#pragma unroll
    for (int kk = 0; kk < 16; kk++) {
        uint32_t af[4], b0[4], b1[4];
        ldsm4(af, aaddr + kk * 32);
        ldsm4(b0, baddr0 + kk * 32);
        ldsm4(b1, baddr1 + kk * 32);
        mma16816(acc[0], af, b0[0], b0[1]);
        mma16816(acc[1], af, b0[2], b0[3]);
        mma16816(acc[2], af, b1[0], b1[1]);
        mma16816(acc[3], af, b1[2], b1[3]);
    }
    float lmax = -3.4e38f, ls = 0.f;
#pragma unroll
    for (int i = 0; i < 4; i++)
#pragma unroll
        for (int j = 0; j < 4; j++) { lmax = fmaxf(lmax, acc[i][j]); ls += acc[i][j]; }
    rm[t] = lmax; rs[t] = ls;
    __syncthreads();
    for (int o = 128; o > 0; o >>= 1) {
        if (t < o) { rm[t] = fmaxf(rm[t], rm[t + o]); rs[t] += rs[t + o]; }
        __syncthreads();
    }
    if (t == 0) {
        fus[g * 6 + 2 * s] = 256.f * rm[0];
        fus[g * 6 + 2 * s + 1] = 256.f * rs[0] / 4096.f;
    }
}

// ---- readout, merged via blockIdx.y ----
__global__ void readout_kernel(const float* __restrict__ xmb, float* __restrict__ rb) {
    __shared__ int ord[3];
    int g = blockIdx.x, t = threadIdx.x, z = blockIdx.y;
    const float* xg = xmb + (size_t)z * 4194304 + (size_t)g * N_PG * D_DIM;
    float* r = rb + (size_t)z * 327680;
    float s = 0.f;
    for (int n = 0; n < N_PG; n++) s += xg[n * D_DIM + t];
    r[g * 1280 + t] = s / 64.f;
    r[g * 1280 + 256 + t] = s / 64.f;   // sum as mean; Wf rows x64
    if (t < 32) {
        float v0 = xg[t * D_DIM + 255], v1 = xg[(t + 32) * D_DIM + 255];
        int i0 = t, i1 = t + 32;
        for (int k = 0; k < 3; k++) {
            float cv; int bi;
            if (v0 > v1 || (v0 == v1 && i0 < i1)) { cv = v0; bi = i0; } else { cv = v1; bi = i1; }
            for (int o = 16; o > 0; o >>= 1) {
                float ov = __shfl_down_sync(0xffffffffu, cv, o);
                int oi = __shfl_down_sync(0xffffffffu, bi, o);
                if (ov > cv || (ov == cv && oi < bi)) { cv = ov; bi = oi; }
            }
            bi = __shfl_sync(0xffffffffu, bi, 0);
            if (t == 0) ord[k] = bi;
            if (bi == i0) v0 = -3.4e38f;
            if (bi == i1) v1 = -3.4e38f;
        }
    }
    __syncthreads();
    for (int k = 0; k < 3; k++) r[g * 1280 + 512 + k * 256 + t] = xg[ord[k] * D_DIM + t];
}

// ---- head ----
__global__ void head_kernel(const float* __restrict__ ob,
                            const float* __restrict__ fus, const float* __restrict__ Wo1,
                            const float* __restrict__ bo1, const float* __restrict__ Wo2,
                            const float* __restrict__ bo2, float* __restrict__ out) {
    __shared__ float cat[518];
    __shared__ float r0[256], r1a[256];
    int g = blockIdx.x, t = threadIdx.x;
    cat[t] = ob[g * 256 + t];
    cat[256 + t] = ob[65536 + g * 256 + t];
    if (t < 6) cat[512 + t] = fus[g * 6 + t];
    __syncthreads();
    float h = bo1[t];
    for (int k = 0; k < 518; k++) h += cat[k] * Wo1[k * 256 + t];
    r0[t] = h * Wo2[t * 2];
    r1a[t] = h * Wo2[t * 2 + 1];
    __syncthreads();
    for (int o = 128; o > 0; o >>= 1) {
        if (t < o) { r0[t] += r0[t + o]; r1a[t] += r1a[t + o]; }
        __syncthreads();
    }
    if (t == 0) { out[g * 2] = r0[0] + bo2[0]; out[g * 2 + 1] = r1a[0] + bo2[1]; }
}

extern "C" void kernel_launch(void* const* d_in, const int* in_sizes, int n_in,
                              void* d_out, int out_size) {
    const float* x1 = (const float*)d_in[0];
    const void* ei1 = d_in[1];
    const float* ea1 = (const float*)d_in[2];
    const float* x2 = (const float*)d_in[4];
    const void* ei2 = d_in[5];
    const float* ea2 = (const float*)d_in[6];
    const float* W0_1 = (const float*)d_in[8];  const float* b0_1 = (const float*)d_in[9];
    const float* W0_2 = (const float*)d_in[10]; const float* b0_2 = (const float*)d_in[11];
    const float* Wn1 = (const float*)d_in[12];  const float* We1 = (const float*)d_in[13];
    const float* bm1 = (const float*)d_in[14];  const float* Ws1 = (const float*)d_in[15];
    const float* bs1 = (const float*)d_in[16];
    const float* Wn2 = (const float*)d_in[17];  const float* We2 = (const float*)d_in[18];
    const float* bm2 = (const float*)d_in[19];  const float* Ws2 = (const float*)d_in[20];
    const float* bs2 = (const float*)d_in[21];
    const float* Wf1 = (const float*)d_in[22];  const float* bf1 = (const float*)d_in[23];
    const float* Wf2 = (const float*)d_in[24];  const float* bf2 = (const float*)d_in[25];
    const float* Wo1 = (const float*)d_in[26];  const float* bo1 = (const float*)d_in[27];
    const float* Wo2 = (const float*)d_in[28];  const float* bo2 = (const float*)d_in[29];
    float* out = (float*)d_out;

    void* p;
    cudaGetSymbolAddress(&p, g_yz);   __half* yz = (__half*)p;
    cudaGetSymbolAddress(&p, g_xm);   float* xm = (float*)p;
    cudaGetSymbolAddress(&p, g_wcat); float* wc = (float*)p;
    cudaGetSymbolAddress(&p, g_wf);   float* wf = (float*)p;
    cudaGetSymbolAddress(&p, g_r);    float* r = (float*)p;
    cudaGetSymbolAddress(&p, g_o);    float* o = (float*)p;
    cudaGetSymbolAddress(&p, g_b0p);  float* b0p = (float*)p;
    cudaGetSymbolAddress(&p, g_bmp);  float* bmp = (float*)p;
    cudaGetSymbolAddress(&p, g_bfp);  float* bfp = (float*)p;
    cudaGetSymbolAddress(&p, g_fus);  float* fus = (float*)p;
    cudaGetSymbolAddress(&p, g_ptr1); int* ptr1 = (int*)p;
    cudaGetSymbolAddress(&p, g_ptr2); int* ptr2 = (int*)p;
    cudaGetSymbolAddress(&p, g_pack1); int2* pack1 = (int2*)p;
    cudaGetSymbolAddress(&p, g_pack2); int2* pack2 = (int2*)p;

    cudaFuncSetAttribute(conv_fused, cudaFuncAttributeMaxDynamicSharedMemorySize, CV_SMEM);
    cudaFuncSetAttribute(dotpool_kernel, cudaFuncAttributeMaxDynamicSharedMemorySize, 2 * 64 * 264 * 2);

    // 1: merged setup
    setup_kernel<<<2048, 256>>>(ei1, ei2, ptr1, ptr2, pack1, pack2,
                                Wn1, Ws1, Wn2, Ws2, Wf1, Wf2,
                                b0_1, b0_2, bm1, bm2, bf1, bf2,
                                wc, wf, b0p, bmp, bfp);

    // 2: input layer both mols
    dim3 gT(2, T_TOT / 128, 2);
    hgemm<2, float><<<gT, 256>>>(x1, x2, W0_1, W0_2, b0p, b0p + 256, xm, xm + 4194304,
                                 T_TOT, 256, 128);

    // loop: 3 yz gemm (fp16 out) -> 4 conv (PROFILED) -> dotpool ...
    dim3 gYZ(4, T_TOT / 128, 2);   // N=512, both mols
    for (int s = 0; s < 3; s++) {
        hgemm<0, __half><<<gYZ, 256>>>(xm, xm + 4194304, wc, wc + 131072, nullptr, nullptr,
                                       yz, yz + 8388608, T_TOT, 512, 256);
        conv_fused<<<dim3(B_GR, 2), 256, CV_SMEM>>>(yz, ea1, ea2, We1, We2, bmp,
                                                    ptr1, ptr2, pack1, pack2, bs1, bs2, xm);
        dotpool_kernel<<<B_GR, 256, 2 * 64 * 264 * 2>>>(xm, fus, s);
    }

    // readout / Wf / head
    readout_kernel<<<dim3(B_GR, 2), 256>>>(xm, r);
    dim3 gF(2, 2, 2);
    hgemm<0, float><<<gF, 256>>>(r, r + 327680, wf, wf + 327680, bfp, bfp + 256,
                                 o, o + 65536, 256, 256, 1280);
    head_kernel<<<B_GR, 256>>>(o, fus, Wo1, bo1, Wo2, bo2, out);
}